// round 2
// baseline (speedup 1.0000x reference)
#include <cuda_runtime.h>
#include <math.h>

#define BN 4096      // total nodes (B*N)
#define NN 1024      // nodes per graph
#define KK 128       // neighbours
#define DD 32        // feature dim
#define EH 130       // edge hidden
#define EHP 132      // padded edge hidden (mult of 4)

__device__ float g_feats[2][BN*DD];
__device__ float g_coors[2][BN*2];
__device__ int   g_idx[BN*KK];
__device__ float g_dist[BN*KK];
__device__ float g_A[BN*EHP];
__device__ float g_Bv[BN*EHP];
__device__ float g_msum[BN*DD];

__device__ __forceinline__ float lrelu(float x){ return x > 0.f ? x : 0.1f*x; }

// ---------------- embed: feats0 = lrelu(feat @ W + b) ----------------
__global__ void embed_kernel(const float* __restrict__ feat,
                             const float* __restrict__ w,
                             const float* __restrict__ b){
    __shared__ float f[DD];
    int gi = blockIdx.x, t = threadIdx.x;
    f[t] = feat[gi*DD + t];
    __syncthreads();
    float a = b[t];
    #pragma unroll
    for (int r = 0; r < DD; r++) a += f[r]*w[r*DD + t];
    g_feats[0][gi*DD + t] = lrelu(a);
}

// ---------------- knn: per-row bitonic sort of (dist, idx) keys ----------------
__global__ void knn_kernel(int cur){
    __shared__ float2 sc[NN];
    __shared__ unsigned long long key[NN];
    int gi = blockIdx.x, t = threadIdx.x;     // 512 threads
    int b = gi >> 10, il = gi & 1023;
    const float2* C = (const float2*)(g_coors[cur]) + b*NN;
    for (int x = t; x < NN; x += 512) sc[x] = C[x];
    __syncthreads();
    float2 ci = sc[il];
    for (int x = t; x < NN; x += 512){
        float dx = ci.x - sc[x].x, dy = ci.y - sc[x].y;
        float d = dx*dx + dy*dy;
        key[x] = ((unsigned long long)__float_as_uint(d) << 32) | (unsigned)x;
    }
    __syncthreads();
    for (int k = 2; k <= NN; k <<= 1){
        for (int j = k >> 1; j > 0; j >>= 1){
            for (int x = t; x < NN; x += 512){
                int ixj = x ^ j;
                if (ixj > x){
                    unsigned long long a = key[x], bb = key[ixj];
                    bool up = (x & k) == 0;
                    if ((a > bb) == up){ key[x] = bb; key[ixj] = a; }
                }
            }
            __syncthreads();
        }
    }
    if (t < KK){
        unsigned long long kv = key[t];
        g_idx[gi*KK + t]  = (int)(kv & 0xffffffffull);
        g_dist[gi*KK + t] = __uint_as_float((unsigned)(kv >> 32));
    }
}

// ---------------- per-node edge-MLP input projections ----------------
// A[i] = feats_i @ W1[0:32]  + e1_b   (bias folded)
// Bv[j] = feats_j @ W1[32:64]
__global__ void pre_kernel(int cur, const float* __restrict__ e1w,
                           const float* __restrict__ e1b){
    __shared__ float f[DD];
    int gi = blockIdx.x, t = threadIdx.x;   // 132 threads
    if (t < DD) f[t] = g_feats[cur][gi*DD + t];
    __syncthreads();
    float a = 0.f, bv = 0.f;
    if (t < EH){
        a = e1b[t];
        #pragma unroll
        for (int r = 0; r < DD; r++){
            float fr = f[r];
            a  += fr * e1w[r*EH + t];
            bv += fr * e1w[(DD + r)*EH + t];
        }
    }
    g_A [gi*EHP + t] = a;
    g_Bv[gi*EHP + t] = bv;
}

// ---------------- edge kernel: 1 block per node i, 1 thread per edge k ----------------
__global__ void __launch_bounds__(128)
edge_kernel(int cur,
            const float* __restrict__ e1w, const float* __restrict__ e2w,
            const float* __restrict__ e2b, const float* __restrict__ gw,
            const float* __restrict__ gb,  const float* __restrict__ c1w,
            const float* __restrict__ c1b, const float* __restrict__ c2w,
            const float* __restrict__ c2b, const float* __restrict__ scl){
    __shared__ float sW2[EHP*DD];        // e2 weights [u][dd], padded rows zero
    __shared__ float sC1t[KK*36];        // c1 transposed [v][dd], row stride 36 (16B aligned)
    __shared__ float sA[EHP], sW1c[EHP];
    __shared__ float sC2[KK], sC1b[KK];
    __shared__ float sGw[DD], sE2b[DD];
    __shared__ float sRedM[4][DD];
    __shared__ float sRedC[4][2];

    int gi = blockIdx.x, t = threadIdx.x;
    int b = gi >> 10;

    for (int x = t; x < EHP*DD; x += 128) sW2[x] = (x < EH*DD) ? e2w[x] : 0.f;
    for (int x = t; x < DD*KK; x += 128){ int dd = x >> 7, v = x & 127; sC1t[v*36 + dd] = c1w[x]; }
    // FIX: strided load so entries 128..131 are initialized (block has only 128 threads)
    for (int x = t; x < EHP; x += 128){
        sA[x]   = g_A[gi*EHP + x];
        sW1c[x] = (x < EH) ? e1w[64*EH + x] : 0.f;
    }
    if (t < KK){ sC2[t] = c2w[t]; sC1b[t] = c1b[t]; }
    if (t < DD){ sGw[t] = gw[t]; sE2b[t] = e2b[t]; }
    __syncthreads();

    int   j = g_idx[gi*KK + t];
    float d = g_dist[gi*KK + t];
    const float4* bv4 = (const float4*)(g_Bv + (size_t)(b*NN + j)*EHP);

    float m[DD];
    #pragma unroll
    for (int dd = 0; dd < DD; dd++) m[dd] = sE2b[dd];

    // h1 = lrelu(A_i + B_j + d*w1c); accumulate m += h1 * W2[u][:]
    #pragma unroll 1
    for (int g = 0; g < EHP/4; g++){
        float4 bv = bv4[g];
        float hb[4] = {bv.x, bv.y, bv.z, bv.w};
        #pragma unroll
        for (int s = 0; s < 4; s++){
            int u = 4*g + s;
            float h = lrelu(sA[u] + hb[s] + d*sW1c[u]);
            const float4* w = (const float4*)(sW2 + u*DD);
            #pragma unroll
            for (int q = 0; q < 8; q++){
                float4 ww = w[q];
                m[4*q+0] += h*ww.x; m[4*q+1] += h*ww.y;
                m[4*q+2] += h*ww.z; m[4*q+3] += h*ww.w;
            }
        }
    }
    #pragma unroll
    for (int dd = 0; dd < DD; dd++) m[dd] = lrelu(m[dd]);

    // soft-edge gate
    float gdot = gb[0];
    #pragma unroll
    for (int dd = 0; dd < DD; dd++) gdot += m[dd]*sGw[dd];
    float sg = 1.f/(1.f + expf(-gdot));
    #pragma unroll
    for (int dd = 0; dd < DD; dd++) m[dd] *= sg;

    // coors MLP -> scalar weight
    float cw = c2b[0];
    #pragma unroll 1
    for (int v = 0; v < KK; v++){
        const float4* cc = (const float4*)(sC1t + v*36);
        float cv = sC1b[v];
        #pragma unroll
        for (int q = 0; q < 8; q++){
            float4 ww = cc[q];
            cv += m[4*q+0]*ww.x + m[4*q+1]*ww.y + m[4*q+2]*ww.z + m[4*q+3]*ww.w;
        }
        cw += lrelu(cv)*sC2[v];
    }

    // coordinate contribution
    const float2* Cg = (const float2*)(g_coors[cur]);
    float2 cj = Cg[b*NN + j];
    float2 ci = Cg[gi];
    float rx = ci.x - cj.x, ry = ci.y - cj.y;
    float nrm = fmaxf(sqrtf(rx*rx + ry*ry), 1e-8f);
    float ss = scl[0] / nrm;
    float cx = cw * (rx * ss), cy = cw * (ry * ss);

    // block reduction over K=128 edges (4 warps)
    #pragma unroll
    for (int off = 16; off > 0; off >>= 1){
        #pragma unroll
        for (int dd = 0; dd < DD; dd++) m[dd] += __shfl_xor_sync(0xffffffffu, m[dd], off);
        cx += __shfl_xor_sync(0xffffffffu, cx, off);
        cy += __shfl_xor_sync(0xffffffffu, cy, off);
    }
    int w = t >> 5, lane = t & 31;
    sRedM[w][lane] = m[lane];
    if (lane == 0){ sRedC[w][0] = cx; sRedC[w][1] = cy; }
    __syncthreads();
    if (t < DD)
        g_msum[gi*DD + t] = sRedM[0][t] + sRedM[1][t] + sRedM[2][t] + sRedM[3][t];
    if (t == 0){
        float X = ci.x + sRedC[0][0] + sRedC[1][0] + sRedC[2][0] + sRedC[3][0];
        float Y = ci.y + sRedC[0][1] + sRedC[1][1] + sRedC[2][1] + sRedC[3][1];
        ((float2*)g_coors[cur^1])[gi] = make_float2(X, Y);
    }
}

// ---------------- node MLP + residual ----------------
__global__ void node_kernel(int cur, int last, float* __restrict__ dout,
                            const float* __restrict__ n1w, const float* __restrict__ n1b,
                            const float* __restrict__ n2w, const float* __restrict__ n2b){
    __shared__ float in[2*DD], h[2*DD];
    int gi = blockIdx.x, t = threadIdx.x;   // 64 threads
    in[t] = (t < DD) ? g_feats[cur][gi*DD + t] : g_msum[gi*DD + (t - DD)];
    __syncthreads();
    float a = n1b[t];
    #pragma unroll
    for (int r = 0; r < 2*DD; r++) a += in[r]*n1w[r*64 + t];
    h[t] = lrelu(a);
    __syncthreads();
    if (t < DD){
        float o = n2b[t];
        #pragma unroll
        for (int r = 0; r < 2*DD; r++) o += h[r]*n2w[r*DD + t];
        o += in[t];
        if (last) dout[gi*DD + t] = o;
        else      g_feats[cur^1][gi*DD + t] = o;
    }
}

extern "C" void kernel_launch(void* const* d_in, const int* in_sizes, int n_in,
                              void* d_out, int out_size){
    const float* feat = (const float*)d_in[0];
    const float* coor = (const float*)d_in[1];
    // d_in[2] = batch (equal-size graphs; unused)
    const float* ew  = (const float*)d_in[3];
    const float* eb  = (const float*)d_in[4];
    const float* e1w = (const float*)d_in[5];
    const float* e1b = (const float*)d_in[6];
    const float* e2w = (const float*)d_in[7];
    const float* e2b = (const float*)d_in[8];
    const float* gw  = (const float*)d_in[9];
    const float* gb  = (const float*)d_in[10];
    const float* c1w = (const float*)d_in[11];
    const float* c1b = (const float*)d_in[12];
    const float* c2w = (const float*)d_in[13];
    const float* c2b = (const float*)d_in[14];
    const float* n1w = (const float*)d_in[15];
    const float* n1b = (const float*)d_in[16];
    const float* n2w = (const float*)d_in[17];
    const float* n2b = (const float*)d_in[18];
    const float* scl = (const float*)d_in[19];

    cudaMemcpyToSymbolAsync(g_coors, coor, BN*2*sizeof(float), 0,
                            cudaMemcpyDeviceToDevice, 0);
    embed_kernel<<<BN, DD>>>(feat, ew, eb);

    int cur = 0;
    for (int l = 0; l < 3; l++){
        knn_kernel<<<BN, 512>>>(cur);
        pre_kernel<<<BN, EHP>>>(cur, e1w + l*65*EH, e1b + l*EH);
        edge_kernel<<<BN, 128>>>(cur,
                                 e1w + l*65*EH, e2w + l*EH*DD, e2b + l*DD,
                                 gw + l*DD, gb + l,
                                 c1w + l*DD*KK, c1b + l*KK,
                                 c2w + l*KK, c2b + l, scl + l);
        node_kernel<<<BN, 2*DD>>>(cur, l == 2, (float*)d_out,
                                  n1w + l*64*64, n1b + l*64,
                                  n2w + l*64*DD, n2b + l*DD);
        cur ^= 1;
    }
}

// round 3
// speedup vs baseline: 1.1670x; 1.1670x over previous
#include <cuda_runtime.h>
#include <math.h>

#define BN 4096      // total nodes (B*N)
#define NN 1024      // nodes per graph
#define KK 128       // neighbours
#define DD 32        // feature dim
#define EH 130       // edge hidden
#define EHP 132      // padded edge hidden (mult of 4)

typedef unsigned long long u64;

__device__ float g_feats[2][BN*DD];
__device__ float g_coors[2][BN*2];
__device__ int   g_idx[BN*KK];
__device__ float g_dist[BN*KK];
__device__ float g_A[BN*EHP];
__device__ float g_Bv[BN*EHP];
__device__ float g_msum[BN*DD];

__device__ __forceinline__ float lrelu(float x){ return fmaxf(x, 0.1f*x); }

__device__ __forceinline__ u64 pk2(float lo, float hi){
    u64 r; asm("mov.b64 %0, {%1,%2};" : "=l"(r) : "f"(lo), "f"(hi)); return r;
}
__device__ __forceinline__ float2 upk2(u64 v){
    float2 f; asm("mov.b64 {%0,%1}, %2;" : "=f"(f.x), "=f"(f.y) : "l"(v)); return f;
}
__device__ __forceinline__ u64 fma2_(u64 a, u64 b, u64 c){
    u64 d; asm("fma.rn.f32x2 %0, %1, %2, %3;" : "=l"(d) : "l"(a), "l"(b), "l"(c)); return d;
}
__device__ __forceinline__ u64 add2_(u64 a, u64 b){
    u64 d; asm("add.rn.f32x2 %0, %1, %2;" : "=l"(d) : "l"(a), "l"(b)); return d;
}
__device__ __forceinline__ u64 mul2_(u64 a, u64 b){
    u64 d; asm("mul.rn.f32x2 %0, %1, %2;" : "=l"(d) : "l"(a), "l"(b)); return d;
}

// ---------------- embed: feats0 = lrelu(feat @ W + b) ----------------
__global__ void embed_kernel(const float* __restrict__ feat,
                             const float* __restrict__ w,
                             const float* __restrict__ b){
    __shared__ float f[DD];
    int gi = blockIdx.x, t = threadIdx.x;
    f[t] = feat[gi*DD + t];
    __syncthreads();
    float a = b[t];
    #pragma unroll
    for (int r = 0; r < DD; r++) a += f[r]*w[r*DD + t];
    g_feats[0][gi*DD + t] = lrelu(a);
}

// ---------------- knn: per-row bitonic sort of (dist, idx) keys ----------------
__global__ void knn_kernel(int cur){
    __shared__ float2 sc[NN];
    __shared__ unsigned long long key[NN];
    int gi = blockIdx.x, t = threadIdx.x;     // 512 threads
    int b = gi >> 10, il = gi & 1023;
    const float2* C = (const float2*)(g_coors[cur]) + b*NN;
    for (int x = t; x < NN; x += 512) sc[x] = C[x];
    __syncthreads();
    float2 ci = sc[il];
    for (int x = t; x < NN; x += 512){
        float dx = ci.x - sc[x].x, dy = ci.y - sc[x].y;
        float d = dx*dx + dy*dy;
        key[x] = ((unsigned long long)__float_as_uint(d) << 32) | (unsigned)x;
    }
    __syncthreads();
    for (int k = 2; k <= NN; k <<= 1){
        for (int j = k >> 1; j > 0; j >>= 1){
            for (int x = t; x < NN; x += 512){
                int ixj = x ^ j;
                if (ixj > x){
                    unsigned long long a = key[x], bb = key[ixj];
                    bool up = (x & k) == 0;
                    if ((a > bb) == up){ key[x] = bb; key[ixj] = a; }
                }
            }
            __syncthreads();
        }
    }
    if (t < KK){
        unsigned long long kv = key[t];
        g_idx[gi*KK + t]  = (int)(kv & 0xffffffffull);
        g_dist[gi*KK + t] = __uint_as_float((unsigned)(kv >> 32));
    }
}

// ---------------- per-node edge-MLP input projections ----------------
__global__ void pre_kernel(int cur, const float* __restrict__ e1w,
                           const float* __restrict__ e1b){
    __shared__ float f[DD];
    int gi = blockIdx.x, t = threadIdx.x;   // 132 threads
    if (t < DD) f[t] = g_feats[cur][gi*DD + t];
    __syncthreads();
    float a = 0.f, bv = 0.f;
    if (t < EH){
        a = e1b[t];
        #pragma unroll
        for (int r = 0; r < DD; r++){
            float fr = f[r];
            a  += fr * e1w[r*EH + t];
            bv += fr * e1w[(DD + r)*EH + t];
        }
    }
    g_A [gi*EHP + t] = a;
    g_Bv[gi*EHP + t] = bv;
}

// ---------------- edge tail: lrelu, gate, c1 MLP -> coordinate weight ----------------
__device__ __forceinline__ float edge_tail(u64* m, const u64* gw2, float gb0,
                                           const float* sC1t, const float* sC1b,
                                           const float* sC2, float c2b0){
    #pragma unroll
    for (int q = 0; q < 16; q++){
        float2 f = upk2(m[q]);
        f.x = lrelu(f.x); f.y = lrelu(f.y);
        m[q] = pk2(f.x, f.y);
    }
    // soft-edge gate
    u64 acc = 0ull;
    #pragma unroll
    for (int q = 0; q < 16; q++) acc = fma2_(m[q], gw2[q], acc);
    float2 af = upk2(acc);
    float gdot = gb0 + af.x + af.y;
    float sg = 1.f/(1.f + expf(-gdot));
    u64 sg2 = pk2(sg, sg);
    #pragma unroll
    for (int q = 0; q < 16; q++) m[q] = mul2_(m[q], sg2);
    // coors MLP -> scalar weight
    float cw = c2b0;
    #pragma unroll 1
    for (int v = 0; v < KK; v++){
        const ulonglong2* cc = (const ulonglong2*)(sC1t + v*36);
        u64 a2 = 0ull;
        #pragma unroll
        for (int q = 0; q < 8; q++){
            ulonglong2 ww = cc[q];
            a2 = fma2_(m[2*q],   ww.x, a2);
            a2 = fma2_(m[2*q+1], ww.y, a2);
        }
        float2 cf = upk2(a2);
        float cv = sC1b[v] + cf.x + cf.y;
        cw += lrelu(cv)*sC2[v];
    }
    return cw;
}

// ---------------- edge kernel: 2 nodes/block, 2 edges/thread ----------------
__global__ void __launch_bounds__(128)
edge_kernel(int cur,
            const float* __restrict__ e1w, const float* __restrict__ e2w,
            const float* __restrict__ e2b, const float* __restrict__ gw,
            const float* __restrict__ gb,  const float* __restrict__ c1w,
            const float* __restrict__ c1b, const float* __restrict__ c2w,
            const float* __restrict__ c2b, const float* __restrict__ scl){
    __shared__ __align__(16) float sW2[EHP*DD];     // e2 weights [u][dd]
    __shared__ __align__(16) float sC1t[KK*36];     // c1 transposed [v][dd], stride 36
    __shared__ __align__(16) float sA[2][EHP];
    __shared__ __align__(16) float sW1c[EHP];
    __shared__ __align__(16) float sC2[KK];
    __shared__ __align__(16) float sC1b[KK];
    __shared__ __align__(16) float sGw[DD];
    __shared__ __align__(16) float sE2b[DD];
    __shared__ __align__(16) u64 sRedM[4][16];
    __shared__ float sRedC[4][2];

    int t = threadIdx.x;
    int nl = t >> 6;                 // node within block (0/1)
    int e0 = t & 63, e1 = e0 + 64;
    int gi_base = blockIdx.x*2;
    int gi = gi_base + nl;
    int b = gi >> 10;

    for (int x = t; x < EHP*DD; x += 128) sW2[x] = (x < EH*DD) ? e2w[x] : 0.f;
    for (int x = t; x < DD*KK; x += 128){ int dd = x >> 7, v = x & 127; sC1t[v*36 + dd] = c1w[x]; }
    for (int x = t; x < 2*EHP; x += 128){
        int n = (x >= EHP) ? 1 : 0;
        int u = x - n*EHP;
        sA[n][u] = g_A[(gi_base + n)*EHP + u];
    }
    for (int x = t; x < EHP; x += 128) sW1c[x] = (x < EH) ? e1w[64*EH + x] : 0.f;
    if (t < KK){ sC2[t] = c2w[t]; sC1b[t] = c1b[t]; }
    if (t < DD){ sGw[t] = gw[t]; sE2b[t] = e2b[t]; }
    __syncthreads();

    int   j0 = g_idx[gi*KK + e0],  j1 = g_idx[gi*KK + e1];
    float d0 = g_dist[gi*KK + e0], d1 = g_dist[gi*KK + e1];
    const float4* bvA = (const float4*)(g_Bv + (size_t)(b*NN + j0)*EHP);
    const float4* bvB = (const float4*)(g_Bv + (size_t)(b*NN + j1)*EHP);
    const float4* a4p = (const float4*)(sA[nl]);
    const float4* w4p = (const float4*)(sW1c);
    const u64* gw2 = (const u64*)sGw;

    u64 m0[16], m1[16];
    {
        const u64* b2 = (const u64*)sE2b;
        #pragma unroll
        for (int q = 0; q < 16; q++){ m0[q] = b2[q]; m1[q] = b2[q]; }
    }

    // h = lrelu(A_i[u] + B_j[u] + d*w1c[u]);  m += h * W2[u][:]
    #pragma unroll 1
    for (int g = 0; g < EHP/4; g++){
        float4 bv0 = bvA[g], bv1 = bvB[g];
        float4 aa = a4p[g],  wc = w4p[g];
        float av[4] = {aa.x, aa.y, aa.z, aa.w};
        float wv[4] = {wc.x, wc.y, wc.z, wc.w};
        float b0v[4] = {bv0.x, bv0.y, bv0.z, bv0.w};
        float b1v[4] = {bv1.x, bv1.y, bv1.z, bv1.w};
        #pragma unroll
        for (int s = 0; s < 4; s++){
            int u = 4*g + s;
            float base = fmaf(d0, wv[s], av[s]);
            float h0 = lrelu(base + b0v[s]);
            float h1 = lrelu(fmaf(d1, wv[s], av[s]) + b1v[s]);
            u64 h02 = pk2(h0, h0), h12 = pk2(h1, h1);
            const ulonglong2* w2 = (const ulonglong2*)(sW2 + u*DD);
            #pragma unroll
            for (int q = 0; q < 8; q++){
                ulonglong2 ww = w2[q];
                m0[2*q]   = fma2_(h02, ww.x, m0[2*q]);
                m0[2*q+1] = fma2_(h02, ww.y, m0[2*q+1]);
                m1[2*q]   = fma2_(h12, ww.x, m1[2*q]);
                m1[2*q+1] = fma2_(h12, ww.y, m1[2*q+1]);
            }
        }
    }

    float gb0 = gb[0], c2b0 = c2b[0], sscl = scl[0];
    float cw0 = edge_tail(m0, gw2, gb0, sC1t, sC1b, sC2, c2b0);
    float cw1 = edge_tail(m1, gw2, gb0, sC1t, sC1b, sC2, c2b0);

    // coordinate contributions
    const float2* Cg = (const float2*)(g_coors[cur]);
    float2 ci = Cg[gi];
    float2 cj0 = Cg[b*NN + j0], cj1 = Cg[b*NN + j1];
    float rx0 = ci.x - cj0.x, ry0 = ci.y - cj0.y;
    float rx1 = ci.x - cj1.x, ry1 = ci.y - cj1.y;
    float n0 = fmaxf(sqrtf(rx0*rx0 + ry0*ry0), 1e-8f);
    float n1 = fmaxf(sqrtf(rx1*rx1 + ry1*ry1), 1e-8f);
    float s0 = sscl/n0, s1 = sscl/n1;
    float cx = cw0*(rx0*s0) + cw1*(rx1*s1);
    float cy = cw0*(ry0*s0) + cw1*(ry1*s1);

    // combine the two edges, then butterfly over the warp
    u64 mt[16];
    #pragma unroll
    for (int q = 0; q < 16; q++) mt[q] = add2_(m0[q], m1[q]);
    u64 cp = pk2(cx, cy);
    #pragma unroll
    for (int off = 16; off > 0; off >>= 1){
        #pragma unroll
        for (int q = 0; q < 16; q++)
            mt[q] = add2_(mt[q], __shfl_xor_sync(0xffffffffu, mt[q], off));
        cp = add2_(cp, __shfl_xor_sync(0xffffffffu, cp, off));
    }
    int w = t >> 5, lane = t & 31;
    if (lane == 0){
        #pragma unroll
        for (int q = 0; q < 16; q++) sRedM[w][q] = mt[q];
        float2 cf = upk2(cp);
        sRedC[w][0] = cf.x; sRedC[w][1] = cf.y;
    }
    __syncthreads();

    // node 0: warps 0-1; node 1: warps 2-3
    if ((t & 63) < 16){
        int n = t >> 6;
        int q = t & 15;
        u64 s = add2_(sRedM[2*n][q], sRedM[2*n+1][q]);
        ((u64*)(g_msum + (size_t)(gi_base + n)*DD))[q] = s;
    }
    if ((t & 63) == 0){
        int n = t >> 6;
        float2 cin = Cg[gi_base + n];
        float X = cin.x + sRedC[2*n][0] + sRedC[2*n+1][0];
        float Y = cin.y + sRedC[2*n][1] + sRedC[2*n+1][1];
        ((float2*)g_coors[cur^1])[gi_base + n] = make_float2(X, Y);
    }
}

// ---------------- node MLP + residual ----------------
__global__ void node_kernel(int cur, int last, float* __restrict__ dout,
                            const float* __restrict__ n1w, const float* __restrict__ n1b,
                            const float* __restrict__ n2w, const float* __restrict__ n2b){
    __shared__ float in[2*DD], h[2*DD];
    int gi = blockIdx.x, t = threadIdx.x;   // 64 threads
    in[t] = (t < DD) ? g_feats[cur][gi*DD + t] : g_msum[gi*DD + (t - DD)];
    __syncthreads();
    float a = n1b[t];
    #pragma unroll
    for (int r = 0; r < 2*DD; r++) a += in[r]*n1w[r*64 + t];
    h[t] = lrelu(a);
    __syncthreads();
    if (t < DD){
        float o = n2b[t];
        #pragma unroll
        for (int r = 0; r < 2*DD; r++) o += h[r]*n2w[r*DD + t];
        o += in[t];
        if (last) dout[gi*DD + t] = o;
        else      g_feats[cur^1][gi*DD + t] = o;
    }
}

extern "C" void kernel_launch(void* const* d_in, const int* in_sizes, int n_in,
                              void* d_out, int out_size){
    const float* feat = (const float*)d_in[0];
    const float* coor = (const float*)d_in[1];
    // d_in[2] = batch (equal-size graphs; unused)
    const float* ew  = (const float*)d_in[3];
    const float* eb  = (const float*)d_in[4];
    const float* e1w = (const float*)d_in[5];
    const float* e1b = (const float*)d_in[6];
    const float* e2w = (const float*)d_in[7];
    const float* e2b = (const float*)d_in[8];
    const float* gw  = (const float*)d_in[9];
    const float* gb  = (const float*)d_in[10];
    const float* c1w = (const float*)d_in[11];
    const float* c1b = (const float*)d_in[12];
    const float* c2w = (const float*)d_in[13];
    const float* c2b = (const float*)d_in[14];
    const float* n1w = (const float*)d_in[15];
    const float* n1b = (const float*)d_in[16];
    const float* n2w = (const float*)d_in[17];
    const float* n2b = (const float*)d_in[18];
    const float* scl = (const float*)d_in[19];

    cudaMemcpyToSymbolAsync(g_coors, coor, BN*2*sizeof(float), 0,
                            cudaMemcpyDeviceToDevice, 0);
    embed_kernel<<<BN, DD>>>(feat, ew, eb);

    int cur = 0;
    for (int l = 0; l < 3; l++){
        knn_kernel<<<BN, 512>>>(cur);
        pre_kernel<<<BN, EHP>>>(cur, e1w + l*65*EH, e1b + l*EH);
        edge_kernel<<<BN/2, 128>>>(cur,
                                 e1w + l*65*EH, e2w + l*EH*DD, e2b + l*DD,
                                 gw + l*DD, gb + l,
                                 c1w + l*DD*KK, c1b + l*KK,
                                 c2w + l*KK, c2b + l, scl + l);
        node_kernel<<<BN, 2*DD>>>(cur, l == 2, (float*)d_out,
                                  n1w + l*64*64, n1b + l*64,
                                  n2w + l*64*DD, n2b + l*DD);
        cur ^= 1;
    }
}

// round 4
// speedup vs baseline: 1.3039x; 1.1172x over previous
#include <cuda_runtime.h>
#include <math.h>

#define BN 4096      // total nodes (B*N)
#define NN 1024      // nodes per graph
#define KK 128       // neighbours
#define DD 32        // feature dim
#define EH 130       // edge hidden
#define EHP 132      // padded edge hidden (mult of 4)

typedef unsigned long long u64;

__device__ float g_feats[2][BN*DD];
__device__ float g_coors[2][BN*2];
__device__ int   g_idx[BN*KK];
__device__ float g_dist[BN*KK];
__device__ float g_A[BN*EHP];
__device__ float g_Bv[BN*EHP];
__device__ float g_msum[BN*DD];

__device__ __forceinline__ float lrelu(float x){ return fmaxf(x, 0.1f*x); }

__device__ __forceinline__ u64 pk2(float lo, float hi){
    u64 r; asm("mov.b64 %0, {%1,%2};" : "=l"(r) : "f"(lo), "f"(hi)); return r;
}
__device__ __forceinline__ float2 upk2(u64 v){
    float2 f; asm("mov.b64 {%0,%1}, %2;" : "=f"(f.x), "=f"(f.y) : "l"(v)); return f;
}
__device__ __forceinline__ u64 fma2_(u64 a, u64 b, u64 c){
    u64 d; asm("fma.rn.f32x2 %0, %1, %2, %3;" : "=l"(d) : "l"(a), "l"(b), "l"(c)); return d;
}
__device__ __forceinline__ u64 add2_(u64 a, u64 b){
    u64 d; asm("add.rn.f32x2 %0, %1, %2;" : "=l"(d) : "l"(a), "l"(b)); return d;
}
__device__ __forceinline__ u64 mul2_(u64 a, u64 b){
    u64 d; asm("mul.rn.f32x2 %0, %1, %2;" : "=l"(d) : "l"(a), "l"(b)); return d;
}

// ---------------- embed: feats0 = lrelu(feat @ W + b) ----------------
__global__ void embed_kernel(const float* __restrict__ feat,
                             const float* __restrict__ w,
                             const float* __restrict__ b){
    __shared__ float f[DD];
    int gi = blockIdx.x, t = threadIdx.x;
    f[t] = feat[gi*DD + t];
    __syncthreads();
    float a = b[t];
    #pragma unroll
    for (int r = 0; r < DD; r++) a += f[r]*w[r*DD + t];
    g_feats[0][gi*DD + t] = lrelu(a);
}

// ---------------- knn: per-row bitonic sort of (dist, idx) keys ----------------
__global__ void knn_kernel(int cur){
    __shared__ float2 sc[NN];
    __shared__ unsigned long long key[NN];
    int gi = blockIdx.x, t = threadIdx.x;     // 512 threads
    int b = gi >> 10, il = gi & 1023;
    const float2* C = (const float2*)(g_coors[cur]) + b*NN;
    for (int x = t; x < NN; x += 512) sc[x] = C[x];
    __syncthreads();
    float2 ci = sc[il];
    for (int x = t; x < NN; x += 512){
        float dx = ci.x - sc[x].x, dy = ci.y - sc[x].y;
        float d = dx*dx + dy*dy;
        key[x] = ((unsigned long long)__float_as_uint(d) << 32) | (unsigned)x;
    }
    __syncthreads();
    for (int k = 2; k <= NN; k <<= 1){
        for (int j = k >> 1; j > 0; j >>= 1){
            for (int x = t; x < NN; x += 512){
                int ixj = x ^ j;
                if (ixj > x){
                    unsigned long long a = key[x], bb = key[ixj];
                    bool up = (x & k) == 0;
                    if ((a > bb) == up){ key[x] = bb; key[ixj] = a; }
                }
            }
            __syncthreads();
        }
    }
    if (t < KK){
        unsigned long long kv = key[t];
        g_idx[gi*KK + t]  = (int)(kv & 0xffffffffull);
        g_dist[gi*KK + t] = __uint_as_float((unsigned)(kv >> 32));
    }
}

// ---------------- per-node edge-MLP input projections ----------------
__global__ void pre_kernel(int cur, const float* __restrict__ e1w,
                           const float* __restrict__ e1b){
    __shared__ float f[DD];
    int gi = blockIdx.x, t = threadIdx.x;   // 132 threads
    if (t < DD) f[t] = g_feats[cur][gi*DD + t];
    __syncthreads();
    float a = 0.f, bv = 0.f;
    if (t < EH){
        a = e1b[t];
        #pragma unroll
        for (int r = 0; r < DD; r++){
            float fr = f[r];
            a  += fr * e1w[r*EH + t];
            bv += fr * e1w[(DD + r)*EH + t];
        }
    }
    g_A [gi*EHP + t] = a;
    g_Bv[gi*EHP + t] = bv;
}

// ---------------- fused edge tail for BOTH edges: lrelu, gate, c1 MLP ----------------
// C1 weight rows are loaded once and feed both edges' accumulators.
__device__ __forceinline__ void edge_tail2(u64* m0, u64* m1, const u64* gw2, float gb0,
                                           const float* sC1t, const float* sC1b,
                                           const float* sC2, float c2b0,
                                           float& cw0o, float& cw1o){
    #pragma unroll
    for (int q = 0; q < 16; q++){
        float2 f0 = upk2(m0[q]), f1 = upk2(m1[q]);
        m0[q] = pk2(lrelu(f0.x), lrelu(f0.y));
        m1[q] = pk2(lrelu(f1.x), lrelu(f1.y));
    }
    // soft-edge gates
    u64 acc0 = 0ull, acc1 = 0ull;
    #pragma unroll
    for (int q = 0; q < 16; q++){
        acc0 = fma2_(m0[q], gw2[q], acc0);
        acc1 = fma2_(m1[q], gw2[q], acc1);
    }
    float2 a0 = upk2(acc0), a1 = upk2(acc1);
    float sg0 = 1.f/(1.f + expf(-(gb0 + a0.x + a0.y)));
    float sg1 = 1.f/(1.f + expf(-(gb0 + a1.x + a1.y)));
    u64 sg02 = pk2(sg0, sg0), sg12 = pk2(sg1, sg1);
    #pragma unroll
    for (int q = 0; q < 16; q++){
        m0[q] = mul2_(m0[q], sg02);
        m1[q] = mul2_(m1[q], sg12);
    }
    // coors MLP -> scalar weights (shared weight loads)
    float cw0 = c2b0, cw1 = c2b0;
    #pragma unroll 1
    for (int v = 0; v < KK; v++){
        const ulonglong2* cc = (const ulonglong2*)(sC1t + v*36);
        u64 s0 = 0ull, s1 = 0ull;
        #pragma unroll
        for (int q = 0; q < 8; q++){
            ulonglong2 ww = cc[q];
            s0 = fma2_(m0[2*q],   ww.x, s0);
            s0 = fma2_(m0[2*q+1], ww.y, s0);
            s1 = fma2_(m1[2*q],   ww.x, s1);
            s1 = fma2_(m1[2*q+1], ww.y, s1);
        }
        float2 f0 = upk2(s0), f1 = upk2(s1);
        float bv = sC1b[v], c2v = sC2[v];
        cw0 += lrelu(bv + f0.x + f0.y)*c2v;
        cw1 += lrelu(bv + f1.x + f1.y)*c2v;
    }
    cw0o = cw0; cw1o = cw1;
}

// ---------------- edge kernel: 2 nodes/block, 2 edges/thread ----------------
__global__ void __launch_bounds__(128)
edge_kernel(int cur,
            const float* __restrict__ e1w, const float* __restrict__ e2w,
            const float* __restrict__ e2b, const float* __restrict__ gw,
            const float* __restrict__ gb,  const float* __restrict__ c1w,
            const float* __restrict__ c1b, const float* __restrict__ c2w,
            const float* __restrict__ c2b, const float* __restrict__ scl){
    __shared__ __align__(16) float sW2[EHP*DD];     // e2 weights [u][dd]
    __shared__ __align__(16) float sC1t[KK*36];     // c1 transposed [v][dd], stride 36
    __shared__ __align__(16) float sA[2][EHP];
    __shared__ __align__(16) float sW1c[EHP];
    __shared__ __align__(16) float sC2[KK];
    __shared__ __align__(16) float sC1b[KK];
    __shared__ __align__(16) float sGw[DD];
    __shared__ __align__(16) float sE2b[DD];
    __shared__ __align__(16) u64 sRedM[4][16];
    __shared__ float sRedC[4][2];

    int t = threadIdx.x;
    int nl = t >> 6;                 // node within block (0/1)
    int e0 = t & 63, e1 = e0 + 64;
    int gi_base = blockIdx.x*2;
    int gi = gi_base + nl;
    int b = gi >> 10;

    for (int x = t; x < EHP*DD; x += 128) sW2[x] = (x < EH*DD) ? e2w[x] : 0.f;
    for (int x = t; x < DD*KK; x += 128){ int dd = x >> 7, v = x & 127; sC1t[v*36 + dd] = c1w[x]; }
    for (int x = t; x < 2*EHP; x += 128){
        int n = (x >= EHP) ? 1 : 0;
        int u = x - n*EHP;
        sA[n][u] = g_A[(gi_base + n)*EHP + u];
    }
    for (int x = t; x < EHP; x += 128) sW1c[x] = (x < EH) ? e1w[64*EH + x] : 0.f;
    if (t < KK){ sC2[t] = c2w[t]; sC1b[t] = c1b[t]; }
    if (t < DD){ sGw[t] = gw[t]; sE2b[t] = e2b[t]; }
    __syncthreads();

    int   j0 = g_idx[gi*KK + e0],  j1 = g_idx[gi*KK + e1];
    float d0 = g_dist[gi*KK + e0], d1 = g_dist[gi*KK + e1];
    const float4* bvA = (const float4*)(g_Bv + (size_t)(b*NN + j0)*EHP);
    const float4* bvB = (const float4*)(g_Bv + (size_t)(b*NN + j1)*EHP);
    const float4* a4p = (const float4*)(sA[nl]);
    const float4* w4p = (const float4*)(sW1c);
    const u64* gw2 = (const u64*)sGw;

    u64 m0[16], m1[16];
    {
        const u64* b2 = (const u64*)sE2b;
        #pragma unroll
        for (int q = 0; q < 16; q++){ m0[q] = b2[q]; m1[q] = b2[q]; }
    }

    // h = lrelu(A_i[u] + B_j[u] + d*w1c[u]);  m += h * W2[u][:]
    #pragma unroll 1
    for (int g = 0; g < EHP/4; g++){
        float4 bv0 = bvA[g], bv1 = bvB[g];
        float4 aa = a4p[g],  wc = w4p[g];
        float av[4] = {aa.x, aa.y, aa.z, aa.w};
        float wv[4] = {wc.x, wc.y, wc.z, wc.w};
        float b0v[4] = {bv0.x, bv0.y, bv0.z, bv0.w};
        float b1v[4] = {bv1.x, bv1.y, bv1.z, bv1.w};
        #pragma unroll
        for (int s = 0; s < 4; s++){
            int u = 4*g + s;
            float h0 = lrelu(fmaf(d0, wv[s], av[s]) + b0v[s]);
            float h1 = lrelu(fmaf(d1, wv[s], av[s]) + b1v[s]);
            u64 h02 = pk2(h0, h0), h12 = pk2(h1, h1);
            const ulonglong2* w2 = (const ulonglong2*)(sW2 + u*DD);
            #pragma unroll
            for (int q = 0; q < 8; q++){
                ulonglong2 ww = w2[q];
                m0[2*q]   = fma2_(h02, ww.x, m0[2*q]);
                m0[2*q+1] = fma2_(h02, ww.y, m0[2*q+1]);
                m1[2*q]   = fma2_(h12, ww.x, m1[2*q]);
                m1[2*q+1] = fma2_(h12, ww.y, m1[2*q+1]);
            }
        }
    }

    float gb0 = gb[0], c2b0 = c2b[0], sscl = scl[0];
    float cw0, cw1;
    edge_tail2(m0, m1, gw2, gb0, sC1t, sC1b, sC2, c2b0, cw0, cw1);

    // coordinate contributions
    const float2* Cg = (const float2*)(g_coors[cur]);
    float2 ci = Cg[gi];
    float2 cj0 = Cg[b*NN + j0], cj1 = Cg[b*NN + j1];
    float rx0 = ci.x - cj0.x, ry0 = ci.y - cj0.y;
    float rx1 = ci.x - cj1.x, ry1 = ci.y - cj1.y;
    float n0 = fmaxf(sqrtf(rx0*rx0 + ry0*ry0), 1e-8f);
    float n1 = fmaxf(sqrtf(rx1*rx1 + ry1*ry1), 1e-8f);
    float s0 = sscl/n0, s1 = sscl/n1;
    float cx = cw0*(rx0*s0) + cw1*(rx1*s1);
    float cy = cw0*(ry0*s0) + cw1*(ry1*s1);

    // combine the two edges, then butterfly over the warp
    u64 mt[16];
    #pragma unroll
    for (int q = 0; q < 16; q++) mt[q] = add2_(m0[q], m1[q]);
    u64 cp = pk2(cx, cy);
    #pragma unroll
    for (int off = 16; off > 0; off >>= 1){
        #pragma unroll
        for (int q = 0; q < 16; q++)
            mt[q] = add2_(mt[q], __shfl_xor_sync(0xffffffffu, mt[q], off));
        cp = add2_(cp, __shfl_xor_sync(0xffffffffu, cp, off));
    }
    int w = t >> 5, lane = t & 31;
    if (lane == 0){
        #pragma unroll
        for (int q = 0; q < 16; q++) sRedM[w][q] = mt[q];
        float2 cf = upk2(cp);
        sRedC[w][0] = cf.x; sRedC[w][1] = cf.y;
    }
    __syncthreads();

    // node 0: warps 0-1; node 1: warps 2-3
    if ((t & 63) < 16){
        int n = t >> 6;
        int q = t & 15;
        u64 s = add2_(sRedM[2*n][q], sRedM[2*n+1][q]);
        ((u64*)(g_msum + (size_t)(gi_base + n)*DD))[q] = s;
    }
    if ((t & 63) == 0){
        int n = t >> 6;
        float2 cin = Cg[gi_base + n];
        float X = cin.x + sRedC[2*n][0] + sRedC[2*n+1][0];
        float Y = cin.y + sRedC[2*n][1] + sRedC[2*n+1][1];
        ((float2*)g_coors[cur^1])[gi_base + n] = make_float2(X, Y);
    }
}

// ---------------- node MLP + residual ----------------
__global__ void node_kernel(int cur, int last, float* __restrict__ dout,
                            const float* __restrict__ n1w, const float* __restrict__ n1b,
                            const float* __restrict__ n2w, const float* __restrict__ n2b){
    __shared__ float in[2*DD], h[2*DD];
    int gi = blockIdx.x, t = threadIdx.x;   // 64 threads
    in[t] = (t < DD) ? g_feats[cur][gi*DD + t] : g_msum[gi*DD + (t - DD)];
    __syncthreads();
    float a = n1b[t];
    #pragma unroll
    for (int r = 0; r < 2*DD; r++) a += in[r]*n1w[r*64 + t];
    h[t] = lrelu(a);
    __syncthreads();
    if (t < DD){
        float o = n2b[t];
        #pragma unroll
        for (int r = 0; r < 2*DD; r++) o += h[r]*n2w[r*DD + t];
        o += in[t];
        if (last) dout[gi*DD + t] = o;
        else      g_feats[cur^1][gi*DD + t] = o;
    }
}

extern "C" void kernel_launch(void* const* d_in, const int* in_sizes, int n_in,
                              void* d_out, int out_size){
    const float* feat = (const float*)d_in[0];
    const float* coor = (const float*)d_in[1];
    // d_in[2] = batch (equal-size graphs; unused)
    const float* ew  = (const float*)d_in[3];
    const float* eb  = (const float*)d_in[4];
    const float* e1w = (const float*)d_in[5];
    const float* e1b = (const float*)d_in[6];
    const float* e2w = (const float*)d_in[7];
    const float* e2b = (const float*)d_in[8];
    const float* gw  = (const float*)d_in[9];
    const float* gb  = (const float*)d_in[10];
    const float* c1w = (const float*)d_in[11];
    const float* c1b = (const float*)d_in[12];
    const float* c2w = (const float*)d_in[13];
    const float* c2b = (const float*)d_in[14];
    const float* n1w = (const float*)d_in[15];
    const float* n1b = (const float*)d_in[16];
    const float* n2w = (const float*)d_in[17];
    const float* n2b = (const float*)d_in[18];
    const float* scl = (const float*)d_in[19];

    cudaMemcpyToSymbolAsync(g_coors, coor, BN*2*sizeof(float), 0,
                            cudaMemcpyDeviceToDevice, 0);
    embed_kernel<<<BN, DD>>>(feat, ew, eb);

    int cur = 0;
    for (int l = 0; l < 3; l++){
        knn_kernel<<<BN, 512>>>(cur);
        pre_kernel<<<BN, EHP>>>(cur, e1w + l*65*EH, e1b + l*EH);
        edge_kernel<<<BN/2, 128>>>(cur,
                                 e1w + l*65*EH, e2w + l*EH*DD, e2b + l*DD,
                                 gw + l*DD, gb + l,
                                 c1w + l*DD*KK, c1b + l*KK,
                                 c2w + l*KK, c2b + l, scl + l);
        node_kernel<<<BN, 2*DD>>>(cur, l == 2, (float*)d_out,
                                  n1w + l*64*64, n1b + l*64,
                                  n2w + l*64*DD, n2b + l*DD);
        cur ^= 1;
    }
}

// round 5
// speedup vs baseline: 1.8303x; 1.4038x over previous
#include <cuda_runtime.h>
#include <math.h>

#define BN 4096      // total nodes (B*N)
#define NN 1024      // nodes per graph
#define KK 128       // neighbours
#define DD 32        // feature dim
#define EH 130       // edge hidden
#define EHP 132      // padded edge hidden (mult of 4)

typedef unsigned long long u64;

__device__ float g_feats[2][BN*DD];
__device__ float g_coors[2][BN*2];
__device__ int   g_idx[BN*KK];
__device__ float g_dist[BN*KK];
__device__ float g_A[BN*EHP];
__device__ float g_Bv[BN*EHP];
__device__ float g_msum[BN*DD];

__device__ __forceinline__ float lrelu(float x){ return fmaxf(x, 0.1f*x); }

__device__ __forceinline__ u64 pk2(float lo, float hi){
    u64 r; asm("mov.b64 %0, {%1,%2};" : "=l"(r) : "f"(lo), "f"(hi)); return r;
}
__device__ __forceinline__ float2 upk2(u64 v){
    float2 f; asm("mov.b64 {%0,%1}, %2;" : "=f"(f.x), "=f"(f.y) : "l"(v)); return f;
}
__device__ __forceinline__ u64 fma2_(u64 a, u64 b, u64 c){
    u64 d; asm("fma.rn.f32x2 %0, %1, %2, %3;" : "=l"(d) : "l"(a), "l"(b), "l"(c)); return d;
}
__device__ __forceinline__ u64 add2_(u64 a, u64 b){
    u64 d; asm("add.rn.f32x2 %0, %1, %2;" : "=l"(d) : "l"(a), "l"(b)); return d;
}
__device__ __forceinline__ u64 mul2_(u64 a, u64 b){
    u64 d; asm("mul.rn.f32x2 %0, %1, %2;" : "=l"(d) : "l"(a), "l"(b)); return d;
}

// ---------------- embed: feats0 = lrelu(feat @ W + b), 4 nodes/block ----------------
__global__ void __launch_bounds__(128)
embed_kernel(const float* __restrict__ feat,
             const float* __restrict__ w,
             const float* __restrict__ b){
    __shared__ float f[4][DD];
    int t = threadIdx.x;
    int n = t >> 5, u = t & 31;
    int gi = blockIdx.x*4 + n;
    f[n][u] = feat[gi*DD + u];
    __syncthreads();
    float a = b[u];
    #pragma unroll
    for (int r = 0; r < DD; r++) a += f[n][r]*w[r*DD + u];
    g_feats[0][gi*DD + u] = lrelu(a);
}

// ---------------- knn: exact top-128 via 10-bit radix select ----------------
// Set of 128 smallest (dist_bits<<32 | idx) keys == reference top_k set (keys unique).
// Output order is deterministic (ballot prefix scans) but not sorted — downstream
// uses are sums over K, so order is irrelevant.
__global__ void __launch_bounds__(256) knn_kernel(int cur){
    __shared__ float2 sc[NN];
    __shared__ unsigned int hist[1024];
    __shared__ u64 cand[NN];
    __shared__ unsigned int sWarp[8][2];
    __shared__ unsigned int sScan[8];
    __shared__ unsigned int sT, sNeed;

    int gi = blockIdx.x, t = threadIdx.x;      // 256 threads
    int b = gi >> 10, il = gi & 1023;
    const float2* C = (const float2*)(g_coors[cur]) + b*NN;
    for (int x = t; x < NN; x += 256) sc[x] = C[x];
    for (int x = t; x < 1024; x += 256) hist[x] = 0u;
    __syncthreads();

    float2 ci = sc[il];
    u64 key[4]; unsigned bin[4];
    #pragma unroll
    for (int r = 0; r < 4; r++){
        int x = t + 256*r;
        float dx = ci.x - sc[x].x, dy = ci.y - sc[x].y;
        float d = dx*dx + dy*dy;
        unsigned db = __float_as_uint(d);
        key[r] = ((u64)db << 32) | (unsigned)x;
        bin[r] = min(db >> 22, 1023u);
        atomicAdd(&hist[bin[r]], 1u);
    }
    __syncthreads();

    // block exclusive scan over 1024 bins (4 bins/thread) to find threshold bin
    unsigned lane = t & 31, w = t >> 5;
    unsigned local = hist[4*t] + hist[4*t+1] + hist[4*t+2] + hist[4*t+3];
    unsigned v = local;
    #pragma unroll
    for (int off = 1; off < 32; off <<= 1){
        unsigned nv = __shfl_up_sync(0xffffffffu, v, off);
        if (lane >= off) v += nv;
    }
    if (lane == 31) sScan[w] = v;
    __syncthreads();
    unsigned wb = 0;
    #pragma unroll
    for (int i = 0; i < 8; i++) if (i < (int)w) wb += sScan[i];
    unsigned run = wb + v - local;     // exclusive prefix of this thread's first bin
    #pragma unroll
    for (int q = 0; q < 4; q++){
        unsigned h = hist[4*t + q];
        if (run <= 127u && run + h > 127u){ sT = 4*t + q; sNeed = 128u - run; }
        run += h;
    }
    __syncthreads();
    unsigned T = sT, need = sNeed;

    // deterministic compaction: winners (bin<T) straight to output, bin==T to cand[]
    unsigned winbase = 0, candbase = 0;
    unsigned ltmask = (1u << lane) - 1u;
    #pragma unroll
    for (int r = 0; r < 4; r++){
        bool win = bin[r] < T;
        bool cd  = bin[r] == T;
        unsigned mw = __ballot_sync(0xffffffffu, win);
        unsigned mc = __ballot_sync(0xffffffffu, cd);
        if (lane == 0){ sWarp[w][0] = __popc(mw); sWarp[w][1] = __popc(mc); }
        __syncthreads();
        unsigned bw = winbase, bc = candbase, tw = 0, tc = 0;
        #pragma unroll
        for (int i = 0; i < 8; i++){
            unsigned cw_ = sWarp[i][0], cc_ = sWarp[i][1];
            if (i < (int)w){ bw += cw_; bc += cc_; }
            tw += cw_; tc += cc_;
        }
        if (win){
            unsigned pos = bw + __popc(mw & ltmask);
            g_idx [gi*KK + pos] = (int)(key[r] & 0xffffffffull);
            g_dist[gi*KK + pos] = __uint_as_float((unsigned)(key[r] >> 32));
        }
        if (cd){
            unsigned pos = bc + __popc(mc & ltmask);
            cand[pos] = key[r];
        }
        winbase += tw; candbase += tc;
        __syncthreads();
    }

    // sort only the threshold bin (typically small) and take `need` smallest
    unsigned cntT = candbase;
    unsigned P = 2; while (P < cntT) P <<= 1;
    for (unsigned x = cntT + t; x < P; x += 256) cand[x] = 0xffffffffffffffffull;
    __syncthreads();
    for (unsigned k = 2; k <= P; k <<= 1){
        for (unsigned j = k >> 1; j > 0; j >>= 1){
            for (unsigned x = t; x < P; x += 256){
                unsigned ixj = x ^ j;
                if (ixj > x){
                    u64 a = cand[x], bb = cand[ixj];
                    bool up = (x & k) == 0;
                    if ((a > bb) == up){ cand[x] = bb; cand[ixj] = a; }
                }
            }
            __syncthreads();
        }
    }
    if (t < need){
        u64 kv = cand[t];
        unsigned pos = winbase + t;       // winbase == 128 - need
        g_idx [gi*KK + pos] = (int)(kv & 0xffffffffull);
        g_dist[gi*KK + pos] = __uint_as_float((unsigned)(kv >> 32));
    }
}

// ---------------- per-node edge-MLP input projections (2 nodes/block) ----------------
__global__ void __launch_bounds__(264)
pre_kernel(int cur, const float* __restrict__ e1w,
           const float* __restrict__ e1b){
    __shared__ float f[2][DD];
    int t = threadIdx.x;
    int n = (t >= 132) ? 1 : 0;
    int u = t - n*132;
    int gi = blockIdx.x*2 + n;
    if (u < DD) f[n][u] = g_feats[cur][gi*DD + u];
    __syncthreads();
    float a = 0.f, bv = 0.f;
    if (u < EH){
        a = e1b[u];
        #pragma unroll
        for (int r = 0; r < DD; r++){
            float fr = f[n][r];
            a  += fr * e1w[r*EH + u];
            bv += fr * e1w[(DD + r)*EH + u];
        }
    }
    g_A [gi*EHP + u] = a;
    g_Bv[gi*EHP + u] = bv;
}

// ---------------- fused edge tail for BOTH edges: lrelu, gate, c1 MLP ----------------
__device__ __forceinline__ void edge_tail2(u64* m0, u64* m1, const u64* gw2, float gb0,
                                           const float* sC1t, const float* sC1b,
                                           const float* sC2, float c2b0,
                                           float& cw0o, float& cw1o){
    #pragma unroll
    for (int q = 0; q < 16; q++){
        float2 f0 = upk2(m0[q]), f1 = upk2(m1[q]);
        m0[q] = pk2(lrelu(f0.x), lrelu(f0.y));
        m1[q] = pk2(lrelu(f1.x), lrelu(f1.y));
    }
    u64 acc0 = 0ull, acc1 = 0ull;
    #pragma unroll
    for (int q = 0; q < 16; q++){
        acc0 = fma2_(m0[q], gw2[q], acc0);
        acc1 = fma2_(m1[q], gw2[q], acc1);
    }
    float2 a0 = upk2(acc0), a1 = upk2(acc1);
    float sg0 = 1.f/(1.f + expf(-(gb0 + a0.x + a0.y)));
    float sg1 = 1.f/(1.f + expf(-(gb0 + a1.x + a1.y)));
    u64 sg02 = pk2(sg0, sg0), sg12 = pk2(sg1, sg1);
    #pragma unroll
    for (int q = 0; q < 16; q++){
        m0[q] = mul2_(m0[q], sg02);
        m1[q] = mul2_(m1[q], sg12);
    }
    float cw0 = c2b0, cw1 = c2b0;
    #pragma unroll 1
    for (int v = 0; v < KK; v++){
        const ulonglong2* cc = (const ulonglong2*)(sC1t + v*36);
        u64 s0 = 0ull, s1 = 0ull;
        #pragma unroll
        for (int q = 0; q < 8; q++){
            ulonglong2 ww = cc[q];
            s0 = fma2_(m0[2*q],   ww.x, s0);
            s0 = fma2_(m0[2*q+1], ww.y, s0);
            s1 = fma2_(m1[2*q],   ww.x, s1);
            s1 = fma2_(m1[2*q+1], ww.y, s1);
        }
        float2 f0 = upk2(s0), f1 = upk2(s1);
        float bv = sC1b[v], c2v = sC2[v];
        cw0 += lrelu(bv + f0.x + f0.y)*c2v;
        cw1 += lrelu(bv + f1.x + f1.y)*c2v;
    }
    cw0o = cw0; cw1o = cw1;
}

// ---------------- edge kernel: 2 nodes/block, 2 edges/thread ----------------
__global__ void __launch_bounds__(128)
edge_kernel(int cur,
            const float* __restrict__ e1w, const float* __restrict__ e2w,
            const float* __restrict__ e2b, const float* __restrict__ gw,
            const float* __restrict__ gb,  const float* __restrict__ c1w,
            const float* __restrict__ c1b, const float* __restrict__ c2w,
            const float* __restrict__ c2b, const float* __restrict__ scl){
    __shared__ __align__(16) float sW2[EHP*DD];     // e2 weights [u][dd]
    __shared__ __align__(16) float sC1t[KK*36];     // c1 transposed [v][dd], stride 36
    __shared__ __align__(16) float sA[2][EHP];
    __shared__ __align__(16) float sW1c[EHP];
    __shared__ __align__(16) float sC2[KK];
    __shared__ __align__(16) float sC1b[KK];
    __shared__ __align__(16) float sGw[DD];
    __shared__ __align__(16) float sE2b[DD];
    __shared__ __align__(16) u64 sRedM[4][16];
    __shared__ float sRedC[4][2];

    int t = threadIdx.x;
    int nl = t >> 6;                 // node within block (0/1)
    int e0 = t & 63, e1 = e0 + 64;
    int gi_base = blockIdx.x*2;
    int gi = gi_base + nl;
    int b = gi >> 10;

    for (int x = t; x < EHP*DD; x += 128) sW2[x] = (x < EH*DD) ? e2w[x] : 0.f;
    for (int x = t; x < DD*KK; x += 128){ int dd = x >> 7, v = x & 127; sC1t[v*36 + dd] = c1w[x]; }
    for (int x = t; x < 2*EHP; x += 128){
        int n = (x >= EHP) ? 1 : 0;
        int u = x - n*EHP;
        sA[n][u] = g_A[(gi_base + n)*EHP + u];
    }
    for (int x = t; x < EHP; x += 128) sW1c[x] = (x < EH) ? e1w[64*EH + x] : 0.f;
    if (t < KK){ sC2[t] = c2w[t]; sC1b[t] = c1b[t]; }
    if (t < DD){ sGw[t] = gw[t]; sE2b[t] = e2b[t]; }
    __syncthreads();

    int   j0 = g_idx[gi*KK + e0],  j1 = g_idx[gi*KK + e1];
    float d0 = g_dist[gi*KK + e0], d1 = g_dist[gi*KK + e1];
    const float4* bvA = (const float4*)(g_Bv + (size_t)(b*NN + j0)*EHP);
    const float4* bvB = (const float4*)(g_Bv + (size_t)(b*NN + j1)*EHP);
    const float4* a4p = (const float4*)(sA[nl]);
    const float4* w4p = (const float4*)(sW1c);
    const u64* gw2 = (const u64*)sGw;

    u64 m0[16], m1[16];
    {
        const u64* b2 = (const u64*)sE2b;
        #pragma unroll
        for (int q = 0; q < 16; q++){ m0[q] = b2[q]; m1[q] = b2[q]; }
    }

    // h = lrelu(A_i[u] + B_j[u] + d*w1c[u]);  m += h * W2[u][:]
    #pragma unroll 1
    for (int g = 0; g < EHP/4; g++){
        float4 bv0 = bvA[g], bv1 = bvB[g];
        float4 aa = a4p[g],  wc = w4p[g];
        float av[4] = {aa.x, aa.y, aa.z, aa.w};
        float wv[4] = {wc.x, wc.y, wc.z, wc.w};
        float b0v[4] = {bv0.x, bv0.y, bv0.z, bv0.w};
        float b1v[4] = {bv1.x, bv1.y, bv1.z, bv1.w};
        #pragma unroll
        for (int s = 0; s < 4; s++){
            int u = 4*g + s;
            float h0 = lrelu(fmaf(d0, wv[s], av[s]) + b0v[s]);
            float h1 = lrelu(fmaf(d1, wv[s], av[s]) + b1v[s]);
            u64 h02 = pk2(h0, h0), h12 = pk2(h1, h1);
            const ulonglong2* w2 = (const ulonglong2*)(sW2 + u*DD);
            #pragma unroll
            for (int q = 0; q < 8; q++){
                ulonglong2 ww = w2[q];
                m0[2*q]   = fma2_(h02, ww.x, m0[2*q]);
                m0[2*q+1] = fma2_(h02, ww.y, m0[2*q+1]);
                m1[2*q]   = fma2_(h12, ww.x, m1[2*q]);
                m1[2*q+1] = fma2_(h12, ww.y, m1[2*q+1]);
            }
        }
    }

    float gb0 = gb[0], c2b0 = c2b[0], sscl = scl[0];
    float cw0, cw1;
    edge_tail2(m0, m1, gw2, gb0, sC1t, sC1b, sC2, c2b0, cw0, cw1);

    // coordinate contributions
    const float2* Cg = (const float2*)(g_coors[cur]);
    float2 ci = Cg[gi];
    float2 cj0 = Cg[b*NN + j0], cj1 = Cg[b*NN + j1];
    float rx0 = ci.x - cj0.x, ry0 = ci.y - cj0.y;
    float rx1 = ci.x - cj1.x, ry1 = ci.y - cj1.y;
    float n0 = fmaxf(sqrtf(rx0*rx0 + ry0*ry0), 1e-8f);
    float n1 = fmaxf(sqrtf(rx1*rx1 + ry1*ry1), 1e-8f);
    float s0 = sscl/n0, s1 = sscl/n1;
    float cx = cw0*(rx0*s0) + cw1*(rx1*s1);
    float cy = cw0*(ry0*s0) + cw1*(ry1*s1);

    // combine the two edges, then butterfly over the warp
    u64 mt[16];
    #pragma unroll
    for (int q = 0; q < 16; q++) mt[q] = add2_(m0[q], m1[q]);
    u64 cp = pk2(cx, cy);
    #pragma unroll
    for (int off = 16; off > 0; off >>= 1){
        #pragma unroll
        for (int q = 0; q < 16; q++)
            mt[q] = add2_(mt[q], __shfl_xor_sync(0xffffffffu, mt[q], off));
        cp = add2_(cp, __shfl_xor_sync(0xffffffffu, cp, off));
    }
    int w = t >> 5, lane = t & 31;
    if (lane == 0){
        #pragma unroll
        for (int q = 0; q < 16; q++) sRedM[w][q] = mt[q];
        float2 cf = upk2(cp);
        sRedC[w][0] = cf.x; sRedC[w][1] = cf.y;
    }
    __syncthreads();

    // node 0: warps 0-1; node 1: warps 2-3
    if ((t & 63) < 16){
        int n = t >> 6;
        int q = t & 15;
        u64 s = add2_(sRedM[2*n][q], sRedM[2*n+1][q]);
        ((u64*)(g_msum + (size_t)(gi_base + n)*DD))[q] = s;
    }
    if ((t & 63) == 0){
        int n = t >> 6;
        float2 cin = Cg[gi_base + n];
        float X = cin.x + sRedC[2*n][0] + sRedC[2*n+1][0];
        float Y = cin.y + sRedC[2*n][1] + sRedC[2*n+1][1];
        ((float2*)g_coors[cur^1])[gi_base + n] = make_float2(X, Y);
    }
}

// ---------------- node MLP + residual (2 nodes/block) ----------------
__global__ void __launch_bounds__(128)
node_kernel(int cur, int last, float* __restrict__ dout,
            const float* __restrict__ n1w, const float* __restrict__ n1b,
            const float* __restrict__ n2w, const float* __restrict__ n2b){
    __shared__ float in[2][2*DD], h[2][2*DD];
    int t = threadIdx.x;
    int n = t >> 6, u = t & 63;
    int gi = blockIdx.x*2 + n;
    in[n][u] = (u < DD) ? g_feats[cur][gi*DD + u] : g_msum[gi*DD + (u - DD)];
    __syncthreads();
    float a = n1b[u];
    #pragma unroll
    for (int r = 0; r < 2*DD; r++) a += in[n][r]*n1w[r*64 + u];
    h[n][u] = lrelu(a);
    __syncthreads();
    if (u < DD){
        float o = n2b[u];
        #pragma unroll
        for (int r = 0; r < 2*DD; r++) o += h[n][r]*n2w[r*DD + u];
        o += in[n][u];
        if (last) dout[gi*DD + u] = o;
        else      g_feats[cur^1][gi*DD + u] = o;
    }
}

extern "C" void kernel_launch(void* const* d_in, const int* in_sizes, int n_in,
                              void* d_out, int out_size){
    const float* feat = (const float*)d_in[0];
    const float* coor = (const float*)d_in[1];
    // d_in[2] = batch (equal-size graphs; unused)
    const float* ew  = (const float*)d_in[3];
    const float* eb  = (const float*)d_in[4];
    const float* e1w = (const float*)d_in[5];
    const float* e1b = (const float*)d_in[6];
    const float* e2w = (const float*)d_in[7];
    const float* e2b = (const float*)d_in[8];
    const float* gw  = (const float*)d_in[9];
    const float* gb  = (const float*)d_in[10];
    const float* c1w = (const float*)d_in[11];
    const float* c1b = (const float*)d_in[12];
    const float* c2w = (const float*)d_in[13];
    const float* c2b = (const float*)d_in[14];
    const float* n1w = (const float*)d_in[15];
    const float* n1b = (const float*)d_in[16];
    const float* n2w = (const float*)d_in[17];
    const float* n2b = (const float*)d_in[18];
    const float* scl = (const float*)d_in[19];

    cudaMemcpyToSymbolAsync(g_coors, coor, BN*2*sizeof(float), 0,
                            cudaMemcpyDeviceToDevice, 0);
    embed_kernel<<<BN/4, 128>>>(feat, ew, eb);

    int cur = 0;
    for (int l = 0; l < 3; l++){
        knn_kernel<<<BN, 256>>>(cur);
        pre_kernel<<<BN/2, 264>>>(cur, e1w + l*65*EH, e1b + l*EH);
        edge_kernel<<<BN/2, 128>>>(cur,
                                 e1w + l*65*EH, e2w + l*EH*DD, e2b + l*DD,
                                 gw + l*DD, gb + l,
                                 c1w + l*DD*KK, c1b + l*KK,
                                 c2w + l*KK, c2b + l, scl + l);
        node_kernel<<<BN/2, 128>>>(cur, l == 2, (float*)d_out,
                                  n1w + l*64*64, n1b + l*64,
                                  n2w + l*64*DD, n2b + l*DD);
        cur ^= 1;
    }
}

// round 6
// speedup vs baseline: 2.0441x; 1.1168x over previous
#include <cuda_runtime.h>
#include <math.h>

#define BN 4096      // total nodes (B*N)
#define NN 1024      // nodes per graph
#define KK 128       // neighbours
#define DD 32        // feature dim
#define EH 130       // edge hidden
#define EHP 132      // padded edge hidden (mult of 4)

typedef unsigned long long u64;

__device__ float g_feats[2][BN*DD];
__device__ float g_coors[2][BN*2];
__device__ int   g_idx[BN*KK];
__device__ float g_dist[BN*KK];
__device__ float g_A[BN*EHP];
__device__ float g_Bv[BN*EHP];
__device__ float g_msum[BN*DD];

__device__ __forceinline__ float lrelu(float x){ return fmaxf(x, 0.1f*x); }

__device__ __forceinline__ u64 pk2(float lo, float hi){
    u64 r; asm("mov.b64 %0, {%1,%2};" : "=l"(r) : "f"(lo), "f"(hi)); return r;
}
__device__ __forceinline__ float2 upk2(u64 v){
    float2 f; asm("mov.b64 {%0,%1}, %2;" : "=f"(f.x), "=f"(f.y) : "l"(v)); return f;
}
__device__ __forceinline__ u64 fma2_(u64 a, u64 b, u64 c){
    u64 d; asm("fma.rn.f32x2 %0, %1, %2, %3;" : "=l"(d) : "l"(a), "l"(b), "l"(c)); return d;
}
__device__ __forceinline__ u64 add2_(u64 a, u64 b){
    u64 d; asm("add.rn.f32x2 %0, %1, %2;" : "=l"(d) : "l"(a), "l"(b)); return d;
}
__device__ __forceinline__ u64 mul2_(u64 a, u64 b){
    u64 d; asm("mul.rn.f32x2 %0, %1, %2;" : "=l"(d) : "l"(a), "l"(b)); return d;
}

// ---------------- embed: feats0 = lrelu(feat @ W + b), 4 nodes/block ----------------
__global__ void __launch_bounds__(128)
embed_kernel(const float* __restrict__ feat,
             const float* __restrict__ w,
             const float* __restrict__ b){
    __shared__ float f[4][DD];
    int t = threadIdx.x;
    int n = t >> 5, u = t & 31;
    int gi = blockIdx.x*4 + n;
    f[n][u] = feat[gi*DD + u];
    __syncthreads();
    float a = b[u];
    #pragma unroll
    for (int r = 0; r < DD; r++) a += f[n][r]*w[r*DD + u];
    g_feats[0][gi*DD + u] = lrelu(a);
}

// ---------------- knn: exact top-128 via 10-bit radix select ----------------
__global__ void __launch_bounds__(256) knn_kernel(int cur){
    __shared__ float2 sc[NN];
    __shared__ unsigned int hist[1024];
    __shared__ u64 cand[NN];
    __shared__ unsigned int sWarp[8][2];
    __shared__ unsigned int sScan[8];
    __shared__ unsigned int sT, sNeed;

    int gi = blockIdx.x, t = threadIdx.x;      // 256 threads
    int b = gi >> 10, il = gi & 1023;
    const float2* C = (const float2*)(g_coors[cur]) + b*NN;
    for (int x = t; x < NN; x += 256) sc[x] = C[x];
    for (int x = t; x < 1024; x += 256) hist[x] = 0u;
    __syncthreads();

    float2 ci = sc[il];
    u64 key[4]; unsigned bin[4];
    #pragma unroll
    for (int r = 0; r < 4; r++){
        int x = t + 256*r;
        float dx = ci.x - sc[x].x, dy = ci.y - sc[x].y;
        float d = dx*dx + dy*dy;
        unsigned db = __float_as_uint(d);
        key[r] = ((u64)db << 32) | (unsigned)x;
        bin[r] = min(db >> 22, 1023u);
        atomicAdd(&hist[bin[r]], 1u);
    }
    __syncthreads();

    unsigned lane = t & 31, w = t >> 5;
    unsigned local = hist[4*t] + hist[4*t+1] + hist[4*t+2] + hist[4*t+3];
    unsigned v = local;
    #pragma unroll
    for (int off = 1; off < 32; off <<= 1){
        unsigned nv = __shfl_up_sync(0xffffffffu, v, off);
        if (lane >= off) v += nv;
    }
    if (lane == 31) sScan[w] = v;
    __syncthreads();
    unsigned wb = 0;
    #pragma unroll
    for (int i = 0; i < 8; i++) if (i < (int)w) wb += sScan[i];
    unsigned run = wb + v - local;
    #pragma unroll
    for (int q = 0; q < 4; q++){
        unsigned h = hist[4*t + q];
        if (run <= 127u && run + h > 127u){ sT = 4*t + q; sNeed = 128u - run; }
        run += h;
    }
    __syncthreads();
    unsigned T = sT, need = sNeed;

    unsigned winbase = 0, candbase = 0;
    unsigned ltmask = (1u << lane) - 1u;
    #pragma unroll
    for (int r = 0; r < 4; r++){
        bool win = bin[r] < T;
        bool cd  = bin[r] == T;
        unsigned mw = __ballot_sync(0xffffffffu, win);
        unsigned mc = __ballot_sync(0xffffffffu, cd);
        if (lane == 0){ sWarp[w][0] = __popc(mw); sWarp[w][1] = __popc(mc); }
        __syncthreads();
        unsigned bw = winbase, bc = candbase, tw = 0, tc = 0;
        #pragma unroll
        for (int i = 0; i < 8; i++){
            unsigned cw_ = sWarp[i][0], cc_ = sWarp[i][1];
            if (i < (int)w){ bw += cw_; bc += cc_; }
            tw += cw_; tc += cc_;
        }
        if (win){
            unsigned pos = bw + __popc(mw & ltmask);
            g_idx [gi*KK + pos] = (int)(key[r] & 0xffffffffull);
            g_dist[gi*KK + pos] = __uint_as_float((unsigned)(key[r] >> 32));
        }
        if (cd){
            unsigned pos = bc + __popc(mc & ltmask);
            cand[pos] = key[r];
        }
        winbase += tw; candbase += tc;
        __syncthreads();
    }

    unsigned cntT = candbase;
    unsigned P = 2; while (P < cntT) P <<= 1;
    for (unsigned x = cntT + t; x < P; x += 256) cand[x] = 0xffffffffffffffffull;
    __syncthreads();
    for (unsigned k = 2; k <= P; k <<= 1){
        for (unsigned j = k >> 1; j > 0; j >>= 1){
            for (unsigned x = t; x < P; x += 256){
                unsigned ixj = x ^ j;
                if (ixj > x){
                    u64 a = cand[x], bb = cand[ixj];
                    bool up = (x & k) == 0;
                    if ((a > bb) == up){ cand[x] = bb; cand[ixj] = a; }
                }
            }
            __syncthreads();
        }
    }
    if (t < need){
        u64 kv = cand[t];
        unsigned pos = winbase + t;
        g_idx [gi*KK + pos] = (int)(kv & 0xffffffffull);
        g_dist[gi*KK + pos] = __uint_as_float((unsigned)(kv >> 32));
    }
}

// ---------------- per-node edge-MLP input projections (2 nodes/block) ----------------
__global__ void __launch_bounds__(264)
pre_kernel(int cur, const float* __restrict__ e1w,
           const float* __restrict__ e1b){
    __shared__ float f[2][DD];
    int t = threadIdx.x;
    int n = (t >= 132) ? 1 : 0;
    int u = t - n*132;
    int gi = blockIdx.x*2 + n;
    if (u < DD) f[n][u] = g_feats[cur][gi*DD + u];
    __syncthreads();
    float a = 0.f, bv = 0.f;
    if (u < EH){
        a = e1b[u];
        #pragma unroll
        for (int r = 0; r < DD; r++){
            float fr = f[n][r];
            a  += fr * e1w[r*EH + u];
            bv += fr * e1w[(DD + r)*EH + u];
        }
    }
    g_A [gi*EHP + u] = a;
    g_Bv[gi*EHP + u] = bv;
}

// ---------------- edge kernel: 4 nodes/block (1 warp each), 4 edges/thread ----------------
__global__ void __launch_bounds__(128)
edge_kernel(int cur,
            const float* __restrict__ e1w, const float* __restrict__ e2w,
            const float* __restrict__ e2b, const float* __restrict__ gw,
            const float* __restrict__ gb,  const float* __restrict__ c1w,
            const float* __restrict__ c1b, const float* __restrict__ c2w,
            const float* __restrict__ c2b, const float* __restrict__ scl){
    __shared__ __align__(16) float sW2[EHP*DD];     // e2 weights [u][dd]
    __shared__ __align__(16) float sC1t[KK*36];     // c1 transposed [v][dd], stride 36
    __shared__ __align__(16) float sA[4][EHP];
    __shared__ __align__(16) float sW1c[EHP];
    __shared__ __align__(16) float sC2[KK];
    __shared__ __align__(16) float sC1b[KK];
    __shared__ __align__(16) float sGw[DD];
    __shared__ __align__(16) float sE2b[DD];

    int t = threadIdx.x;
    int w = t >> 5;                    // warp = node within block
    int lane = t & 31;
    int gi = blockIdx.x*4 + w;
    int b = gi >> 10;

    for (int x = t; x < EHP*DD; x += 128) sW2[x] = (x < EH*DD) ? e2w[x] : 0.f;
    for (int x = t; x < DD*KK; x += 128){ int dd = x >> 7, v = x & 127; sC1t[v*36 + dd] = c1w[x]; }
    for (int x = t; x < 4*EHP; x += 128){
        int n = x / EHP, u = x - n*EHP;
        sA[n][u] = g_A[(blockIdx.x*4 + n)*EHP + u];
    }
    for (int x = t; x < EHP; x += 128) sW1c[x] = (x < EH) ? e1w[64*EH + x] : 0.f;
    if (t < KK){ sC2[t] = c2w[t]; sC1b[t] = c1b[t]; }
    if (t < DD){ sGw[t] = gw[t]; sE2b[t] = e2b[t]; }
    __syncthreads();

    int   j[4]; float d[4];
    #pragma unroll
    for (int q = 0; q < 4; q++){
        j[q] = g_idx [gi*KK + lane + 32*q];
        d[q] = g_dist[gi*KK + lane + 32*q];
    }
    const float4* bvP[4];
    #pragma unroll
    for (int q = 0; q < 4; q++)
        bvP[q] = (const float4*)(g_Bv + (size_t)(b*NN + j[q])*EHP);

    const float4* a4p = (const float4*)(sA[w]);
    const float4* w4p = (const float4*)(sW1c);
    const u64* gw2 = (const u64*)sGw;

    u64 m[4][16];
    {
        const u64* b2 = (const u64*)sE2b;
        #pragma unroll
        for (int q = 0; q < 4; q++)
            #pragma unroll
            for (int i = 0; i < 16; i++) m[q][i] = b2[i];
    }

    // h = lrelu(A_i[u] + B_j[u] + d*w1c[u]);  m += h * W2[u][:]
    #pragma unroll 1
    for (int g = 0; g < EHP/4; g++){
        float4 aa = a4p[g], wc = w4p[g];
        float av[4] = {aa.x, aa.y, aa.z, aa.w};
        float wv[4] = {wc.x, wc.y, wc.z, wc.w};
        float bv[4][4];
        #pragma unroll
        for (int q = 0; q < 4; q++){
            float4 bb = bvP[q][g];
            bv[q][0] = bb.x; bv[q][1] = bb.y; bv[q][2] = bb.z; bv[q][3] = bb.w;
        }
        #pragma unroll
        for (int s = 0; s < 4; s++){
            int u = 4*g + s;
            u64 h2[4];
            #pragma unroll
            for (int q = 0; q < 4; q++){
                float h = lrelu(fmaf(d[q], wv[s], av[s]) + bv[q][s]);
                h2[q] = pk2(h, h);
            }
            const ulonglong2* w2 = (const ulonglong2*)(sW2 + u*DD);
            #pragma unroll
            for (int k = 0; k < 8; k++){
                ulonglong2 ww = w2[k];
                #pragma unroll
                for (int q = 0; q < 4; q++){
                    m[q][2*k]   = fma2_(h2[q], ww.x, m[q][2*k]);
                    m[q][2*k+1] = fma2_(h2[q], ww.y, m[q][2*k+1]);
                }
            }
        }
    }

    // lrelu on messages
    #pragma unroll
    for (int q = 0; q < 4; q++)
        #pragma unroll
        for (int i = 0; i < 16; i++){
            float2 f = upk2(m[q][i]);
            m[q][i] = pk2(lrelu(f.x), lrelu(f.y));
        }

    // soft-edge gates
    float gb0 = gb[0];
    {
        u64 acc[4] = {0ull,0ull,0ull,0ull};
        #pragma unroll
        for (int i = 0; i < 16; i++){
            u64 gwv = gw2[i];
            #pragma unroll
            for (int q = 0; q < 4; q++) acc[q] = fma2_(m[q][i], gwv, acc[q]);
        }
        #pragma unroll
        for (int q = 0; q < 4; q++){
            float2 a = upk2(acc[q]);
            float sg = 1.f/(1.f + expf(-(gb0 + a.x + a.y)));
            u64 sg2 = pk2(sg, sg);
            #pragma unroll
            for (int i = 0; i < 16; i++) m[q][i] = mul2_(m[q][i], sg2);
        }
    }

    // coors MLP -> per-edge scalar weight (C1 rows loaded once for 4 edges)
    float c2b0 = c2b[0];
    float cw[4] = {c2b0, c2b0, c2b0, c2b0};
    #pragma unroll 1
    for (int v = 0; v < KK; v++){
        const ulonglong2* cc = (const ulonglong2*)(sC1t + v*36);
        u64 s[4] = {0ull,0ull,0ull,0ull};
        #pragma unroll
        for (int k = 0; k < 8; k++){
            ulonglong2 ww = cc[k];
            #pragma unroll
            for (int q = 0; q < 4; q++){
                s[q] = fma2_(m[q][2*k],   ww.x, s[q]);
                s[q] = fma2_(m[q][2*k+1], ww.y, s[q]);
            }
        }
        float bv = sC1b[v], c2v = sC2[v];
        #pragma unroll
        for (int q = 0; q < 4; q++){
            float2 f = upk2(s[q]);
            cw[q] += lrelu(bv + f.x + f.y)*c2v;
        }
    }

    // coordinate contributions
    const float2* Cg = (const float2*)(g_coors[cur]);
    float2 ci = Cg[gi];
    float sscl = scl[0];
    float cx = 0.f, cy = 0.f;
    #pragma unroll
    for (int q = 0; q < 4; q++){
        float2 cj = Cg[b*NN + j[q]];
        float rx = ci.x - cj.x, ry = ci.y - cj.y;
        float nm = fmaxf(sqrtf(rx*rx + ry*ry), 1e-8f);
        float ss = sscl/nm;
        cx += cw[q]*(rx*ss);
        cy += cw[q]*(ry*ss);
    }

    // warp-level reduction (node fully inside this warp)
    u64 mt[16];
    #pragma unroll
    for (int i = 0; i < 16; i++)
        mt[i] = add2_(add2_(m[0][i], m[1][i]), add2_(m[2][i], m[3][i]));
    u64 cp = pk2(cx, cy);
    #pragma unroll
    for (int off = 16; off > 0; off >>= 1){
        #pragma unroll
        for (int i = 0; i < 16; i++)
            mt[i] = add2_(mt[i], __shfl_xor_sync(0xffffffffu, mt[i], off));
        cp = add2_(cp, __shfl_xor_sync(0xffffffffu, cp, off));
    }
    if (lane < 16)
        ((u64*)(g_msum + (size_t)gi*DD))[lane] = mt[lane];
    if (lane == 0){
        float2 cf = upk2(cp);
        ((float2*)g_coors[cur^1])[gi] = make_float2(ci.x + cf.x, ci.y + cf.y);
    }
}

// ---------------- node MLP + residual (2 nodes/block) ----------------
__global__ void __launch_bounds__(128)
node_kernel(int cur, int last, float* __restrict__ dout,
            const float* __restrict__ n1w, const float* __restrict__ n1b,
            const float* __restrict__ n2w, const float* __restrict__ n2b){
    __shared__ float in[2][2*DD], h[2][2*DD];
    int t = threadIdx.x;
    int n = t >> 6, u = t & 63;
    int gi = blockIdx.x*2 + n;
    in[n][u] = (u < DD) ? g_feats[cur][gi*DD + u] : g_msum[gi*DD + (u - DD)];
    __syncthreads();
    float a = n1b[u];
    #pragma unroll
    for (int r = 0; r < 2*DD; r++) a += in[n][r]*n1w[r*64 + u];
    h[n][u] = lrelu(a);
    __syncthreads();
    if (u < DD){
        float o = n2b[u];
        #pragma unroll
        for (int r = 0; r < 2*DD; r++) o += h[n][r]*n2w[r*DD + u];
        o += in[n][u];
        if (last) dout[gi*DD + u] = o;
        else      g_feats[cur^1][gi*DD + u] = o;
    }
}

extern "C" void kernel_launch(void* const* d_in, const int* in_sizes, int n_in,
                              void* d_out, int out_size){
    const float* feat = (const float*)d_in[0];
    const float* coor = (const float*)d_in[1];
    // d_in[2] = batch (equal-size graphs; unused)
    const float* ew  = (const float*)d_in[3];
    const float* eb  = (const float*)d_in[4];
    const float* e1w = (const float*)d_in[5];
    const float* e1b = (const float*)d_in[6];
    const float* e2w = (const float*)d_in[7];
    const float* e2b = (const float*)d_in[8];
    const float* gw  = (const float*)d_in[9];
    const float* gb  = (const float*)d_in[10];
    const float* c1w = (const float*)d_in[11];
    const float* c1b = (const float*)d_in[12];
    const float* c2w = (const float*)d_in[13];
    const float* c2b = (const float*)d_in[14];
    const float* n1w = (const float*)d_in[15];
    const float* n1b = (const float*)d_in[16];
    const float* n2w = (const float*)d_in[17];
    const float* n2b = (const float*)d_in[18];
    const float* scl = (const float*)d_in[19];

    cudaMemcpyToSymbolAsync(g_coors, coor, BN*2*sizeof(float), 0,
                            cudaMemcpyDeviceToDevice, 0);
    embed_kernel<<<BN/4, 128>>>(feat, ew, eb);

    int cur = 0;
    for (int l = 0; l < 3; l++){
        knn_kernel<<<BN, 256>>>(cur);
        pre_kernel<<<BN/2, 264>>>(cur, e1w + l*65*EH, e1b + l*EH);
        edge_kernel<<<BN/4, 128>>>(cur,
                                 e1w + l*65*EH, e2w + l*EH*DD, e2b + l*DD,
                                 gw + l*DD, gb + l,
                                 c1w + l*DD*KK, c1b + l*KK,
                                 c2w + l*KK, c2b + l, scl + l);
        node_kernel<<<BN/2, 128>>>(cur, l == 2, (float*)d_out,
                                  n1w + l*64*64, n1b + l*64,
                                  n2w + l*64*DD, n2b + l*DD);
        cur ^= 1;
    }
}

// round 7
// speedup vs baseline: 2.2294x; 1.0907x over previous
#include <cuda_runtime.h>
#include <math.h>

#define BN 4096      // total nodes (B*N)
#define NN 1024      // nodes per graph
#define KK 128       // neighbours
#define DD 32        // feature dim
#define EH 130       // edge hidden
#define EHP 132      // padded edge hidden (mult of 4)

typedef unsigned long long u64;

__device__ float g_feats[2][BN*DD];
__device__ float g_coors[2][BN*2];
__device__ int   g_idx[BN*KK];
__device__ float g_dist[BN*KK];
__device__ float g_A[BN*EHP];
__device__ float g_Bv[BN*EHP];
__device__ float g_msum[BN*DD];

__device__ __forceinline__ float lrelu(float x){ return fmaxf(x, 0.1f*x); }

__device__ __forceinline__ u64 pk2(float lo, float hi){
    u64 r; asm("mov.b64 %0, {%1,%2};" : "=l"(r) : "f"(lo), "f"(hi)); return r;
}
__device__ __forceinline__ float2 upk2(u64 v){
    float2 f; asm("mov.b64 {%0,%1}, %2;" : "=f"(f.x), "=f"(f.y) : "l"(v)); return f;
}
__device__ __forceinline__ u64 fma2_(u64 a, u64 b, u64 c){
    u64 d; asm("fma.rn.f32x2 %0, %1, %2, %3;" : "=l"(d) : "l"(a), "l"(b), "l"(c)); return d;
}
__device__ __forceinline__ u64 add2_(u64 a, u64 b){
    u64 d; asm("add.rn.f32x2 %0, %1, %2;" : "=l"(d) : "l"(a), "l"(b)); return d;
}
__device__ __forceinline__ u64 mul2_(u64 a, u64 b){
    u64 d; asm("mul.rn.f32x2 %0, %1, %2;" : "=l"(d) : "l"(a), "l"(b)); return d;
}

// ---------------- embed: feats0 = lrelu(feat @ W + b), 4 nodes/block ----------------
__global__ void __launch_bounds__(128)
embed_kernel(const float* __restrict__ feat,
             const float* __restrict__ w,
             const float* __restrict__ b){
    __shared__ float f[4][DD];
    int t = threadIdx.x;
    int n = t >> 5, u = t & 31;
    int gi = blockIdx.x*4 + n;
    f[n][u] = feat[gi*DD + u];
    __syncthreads();
    float a = b[u];
    #pragma unroll
    for (int r = 0; r < DD; r++) a += f[n][r]*w[r*DD + u];
    g_feats[0][gi*DD + u] = lrelu(a);
}

// ---------------- knn: exact top-128 via 10-bit radix select ----------------
__global__ void __launch_bounds__(256) knn_kernel(int cur){
    __shared__ float2 sc[NN];
    __shared__ unsigned int hist[1024];
    __shared__ u64 cand[NN];
    __shared__ unsigned int sWarp[8][2];
    __shared__ unsigned int sScan[8];
    __shared__ unsigned int sT, sNeed;

    int gi = blockIdx.x, t = threadIdx.x;      // 256 threads
    int b = gi >> 10, il = gi & 1023;
    const float2* C = (const float2*)(g_coors[cur]) + b*NN;
    for (int x = t; x < NN; x += 256) sc[x] = C[x];
    for (int x = t; x < 1024; x += 256) hist[x] = 0u;
    __syncthreads();

    float2 ci = sc[il];
    u64 key[4]; unsigned bin[4];
    #pragma unroll
    for (int r = 0; r < 4; r++){
        int x = t + 256*r;
        float dx = ci.x - sc[x].x, dy = ci.y - sc[x].y;
        float d = dx*dx + dy*dy;
        unsigned db = __float_as_uint(d);
        key[r] = ((u64)db << 32) | (unsigned)x;
        bin[r] = min(db >> 22, 1023u);
        atomicAdd(&hist[bin[r]], 1u);
    }
    __syncthreads();

    unsigned lane = t & 31, w = t >> 5;
    unsigned local = hist[4*t] + hist[4*t+1] + hist[4*t+2] + hist[4*t+3];
    unsigned v = local;
    #pragma unroll
    for (int off = 1; off < 32; off <<= 1){
        unsigned nv = __shfl_up_sync(0xffffffffu, v, off);
        if (lane >= off) v += nv;
    }
    if (lane == 31) sScan[w] = v;
    __syncthreads();
    unsigned wb = 0;
    #pragma unroll
    for (int i = 0; i < 8; i++) if (i < (int)w) wb += sScan[i];
    unsigned run = wb + v - local;
    #pragma unroll
    for (int q = 0; q < 4; q++){
        unsigned h = hist[4*t + q];
        if (run <= 127u && run + h > 127u){ sT = 4*t + q; sNeed = 128u - run; }
        run += h;
    }
    __syncthreads();
    unsigned T = sT, need = sNeed;

    unsigned winbase = 0, candbase = 0;
    unsigned ltmask = (1u << lane) - 1u;
    #pragma unroll
    for (int r = 0; r < 4; r++){
        bool win = bin[r] < T;
        bool cd  = bin[r] == T;
        unsigned mw = __ballot_sync(0xffffffffu, win);
        unsigned mc = __ballot_sync(0xffffffffu, cd);
        if (lane == 0){ sWarp[w][0] = __popc(mw); sWarp[w][1] = __popc(mc); }
        __syncthreads();
        unsigned bw = winbase, bc = candbase, tw = 0, tc = 0;
        #pragma unroll
        for (int i = 0; i < 8; i++){
            unsigned cw_ = sWarp[i][0], cc_ = sWarp[i][1];
            if (i < (int)w){ bw += cw_; bc += cc_; }
            tw += cw_; tc += cc_;
        }
        if (win){
            unsigned pos = bw + __popc(mw & ltmask);
            g_idx [gi*KK + pos] = (int)(key[r] & 0xffffffffull);
            g_dist[gi*KK + pos] = __uint_as_float((unsigned)(key[r] >> 32));
        }
        if (cd){
            unsigned pos = bc + __popc(mc & ltmask);
            cand[pos] = key[r];
        }
        winbase += tw; candbase += tc;
        __syncthreads();
    }

    unsigned cntT = candbase;
    unsigned P = 2; while (P < cntT) P <<= 1;
    for (unsigned x = cntT + t; x < P; x += 256) cand[x] = 0xffffffffffffffffull;
    __syncthreads();
    for (unsigned k = 2; k <= P; k <<= 1){
        for (unsigned j = k >> 1; j > 0; j >>= 1){
            for (unsigned x = t; x < P; x += 256){
                unsigned ixj = x ^ j;
                if (ixj > x){
                    u64 a = cand[x], bb = cand[ixj];
                    bool up = (x & k) == 0;
                    if ((a > bb) == up){ cand[x] = bb; cand[ixj] = a; }
                }
            }
            __syncthreads();
        }
    }
    if (t < need){
        u64 kv = cand[t];
        unsigned pos = winbase + t;
        g_idx [gi*KK + pos] = (int)(kv & 0xffffffffull);
        g_dist[gi*KK + pos] = __uint_as_float((unsigned)(kv >> 32));
    }
}

// ---------------- per-node edge-MLP input projections (2 nodes/block) ----------------
__global__ void __launch_bounds__(264)
pre_kernel(int cur, const float* __restrict__ e1w,
           const float* __restrict__ e1b){
    __shared__ float f[2][DD];
    int t = threadIdx.x;
    int n = (t >= 132) ? 1 : 0;
    int u = t - n*132;
    int gi = blockIdx.x*2 + n;
    if (u < DD) f[n][u] = g_feats[cur][gi*DD + u];
    __syncthreads();
    float a = 0.f, bv = 0.f;
    if (u < EH){
        a = e1b[u];
        #pragma unroll
        for (int r = 0; r < DD; r++){
            float fr = f[n][r];
            a  += fr * e1w[r*EH + u];
            bv += fr * e1w[(DD + r)*EH + u];
        }
    }
    g_A [gi*EHP + u] = a;
    g_Bv[gi*EHP + u] = bv;
}

// ---------------- edge kernel: 4 nodes/block (1 warp each), 4 edges/thread ----------------
// Software-pipelined: Bv rows for iteration g+1 prefetched during iteration g.
__global__ void __launch_bounds__(128)
edge_kernel(int cur,
            const float* __restrict__ e1w, const float* __restrict__ e2w,
            const float* __restrict__ e2b, const float* __restrict__ gw,
            const float* __restrict__ gb,  const float* __restrict__ c1w,
            const float* __restrict__ c1b, const float* __restrict__ c2w,
            const float* __restrict__ c2b, const float* __restrict__ scl){
    __shared__ __align__(16) float sW2[EHP*DD];     // e2 weights [u][dd]
    __shared__ __align__(16) float sC1t[KK*36];     // c1 transposed [v][dd], stride 36
    __shared__ __align__(16) float sA[4][EHP];
    __shared__ __align__(16) float sW1c[EHP];
    __shared__ __align__(16) float sC2[KK];
    __shared__ __align__(16) float sC1b[KK];
    __shared__ __align__(16) float sGw[DD];
    __shared__ __align__(16) float sE2b[DD];

    int t = threadIdx.x;
    int w = t >> 5;                    // warp = node within block
    int lane = t & 31;
    int gi = blockIdx.x*4 + w;
    int b = gi >> 10;

    for (int x = t; x < EHP*DD; x += 128) sW2[x] = (x < EH*DD) ? e2w[x] : 0.f;
    for (int x = t; x < DD*KK; x += 128){ int dd = x >> 7, v = x & 127; sC1t[v*36 + dd] = c1w[x]; }
    for (int x = t; x < 4*EHP; x += 128){
        int n = x / EHP, u = x - n*EHP;
        sA[n][u] = g_A[(blockIdx.x*4 + n)*EHP + u];
    }
    for (int x = t; x < EHP; x += 128) sW1c[x] = (x < EH) ? e1w[64*EH + x] : 0.f;
    if (t < KK){ sC2[t] = c2w[t]; sC1b[t] = c1b[t]; }
    if (t < DD){ sGw[t] = gw[t]; sE2b[t] = e2b[t]; }
    __syncthreads();

    int   j[4]; float d[4];
    #pragma unroll
    for (int q = 0; q < 4; q++){
        j[q] = g_idx [gi*KK + lane + 32*q];
        d[q] = g_dist[gi*KK + lane + 32*q];
    }
    const float4* bvP[4];
    #pragma unroll
    for (int q = 0; q < 4; q++)
        bvP[q] = (const float4*)(g_Bv + (size_t)(b*NN + j[q])*EHP);

    const float4* a4p = (const float4*)(sA[w]);
    const float4* w4p = (const float4*)(sW1c);
    const u64* gw2 = (const u64*)sGw;

    u64 m[4][16];
    {
        const u64* b2 = (const u64*)sE2b;
        #pragma unroll
        for (int q = 0; q < 4; q++)
            #pragma unroll
            for (int i = 0; i < 16; i++) m[q][i] = b2[i];
    }

    // software-pipelined main loop
    float4 bvCur[4];
    #pragma unroll
    for (int q = 0; q < 4; q++) bvCur[q] = bvP[q][0];

    #pragma unroll 1
    for (int g = 0; g < EHP/4; g++){
        float4 bvNext[4];
        if (g + 1 < EHP/4){
            #pragma unroll
            for (int q = 0; q < 4; q++) bvNext[q] = bvP[q][g+1];
        }
        float4 aa = a4p[g], wc = w4p[g];
        float av[4] = {aa.x, aa.y, aa.z, aa.w};
        float wv[4] = {wc.x, wc.y, wc.z, wc.w};
        float bv[4][4];
        #pragma unroll
        for (int q = 0; q < 4; q++){
            bv[q][0] = bvCur[q].x; bv[q][1] = bvCur[q].y;
            bv[q][2] = bvCur[q].z; bv[q][3] = bvCur[q].w;
        }
        #pragma unroll
        for (int s = 0; s < 4; s++){
            int u = 4*g + s;
            u64 h2[4];
            #pragma unroll
            for (int q = 0; q < 4; q++){
                float h = lrelu(fmaf(d[q], wv[s], av[s]) + bv[q][s]);
                h2[q] = pk2(h, h);
            }
            const ulonglong2* w2 = (const ulonglong2*)(sW2 + u*DD);
            #pragma unroll
            for (int k = 0; k < 8; k++){
                ulonglong2 ww = w2[k];
                #pragma unroll
                for (int q = 0; q < 4; q++){
                    m[q][2*k]   = fma2_(h2[q], ww.x, m[q][2*k]);
                    m[q][2*k+1] = fma2_(h2[q], ww.y, m[q][2*k+1]);
                }
            }
        }
        #pragma unroll
        for (int q = 0; q < 4; q++) bvCur[q] = bvNext[q];
    }

    // lrelu on messages
    #pragma unroll
    for (int q = 0; q < 4; q++)
        #pragma unroll
        for (int i = 0; i < 16; i++){
            float2 f = upk2(m[q][i]);
            m[q][i] = pk2(lrelu(f.x), lrelu(f.y));
        }

    // soft-edge gates
    float gb0 = gb[0];
    {
        u64 acc[4] = {0ull,0ull,0ull,0ull};
        #pragma unroll
        for (int i = 0; i < 16; i++){
            u64 gwv = gw2[i];
            #pragma unroll
            for (int q = 0; q < 4; q++) acc[q] = fma2_(m[q][i], gwv, acc[q]);
        }
        #pragma unroll
        for (int q = 0; q < 4; q++){
            float2 a = upk2(acc[q]);
            float sg = 1.f/(1.f + expf(-(gb0 + a.x + a.y)));
            u64 sg2 = pk2(sg, sg);
            #pragma unroll
            for (int i = 0; i < 16; i++) m[q][i] = mul2_(m[q][i], sg2);
        }
    }

    // coors MLP -> per-edge scalar weight (C1 rows loaded once for 4 edges)
    float c2b0 = c2b[0];
    float cw[4] = {c2b0, c2b0, c2b0, c2b0};
    #pragma unroll 1
    for (int v = 0; v < KK; v++){
        const ulonglong2* cc = (const ulonglong2*)(sC1t + v*36);
        u64 s[4] = {0ull,0ull,0ull,0ull};
        #pragma unroll
        for (int k = 0; k < 8; k++){
            ulonglong2 ww = cc[k];
            #pragma unroll
            for (int q = 0; q < 4; q++){
                s[q] = fma2_(m[q][2*k],   ww.x, s[q]);
                s[q] = fma2_(m[q][2*k+1], ww.y, s[q]);
            }
        }
        float bv = sC1b[v], c2v = sC2[v];
        #pragma unroll
        for (int q = 0; q < 4; q++){
            float2 f = upk2(s[q]);
            cw[q] += lrelu(bv + f.x + f.y)*c2v;
        }
    }

    // coordinate contributions
    const float2* Cg = (const float2*)(g_coors[cur]);
    float2 ci = Cg[gi];
    float sscl = scl[0];
    float cx = 0.f, cy = 0.f;
    #pragma unroll
    for (int q = 0; q < 4; q++){
        float2 cj = Cg[b*NN + j[q]];
        float rx = ci.x - cj.x, ry = ci.y - cj.y;
        float nm = fmaxf(sqrtf(rx*rx + ry*ry), 1e-8f);
        float ss = sscl/nm;
        cx += cw[q]*(rx*ss);
        cy += cw[q]*(ry*ss);
    }

    // warp-level reduction (node fully inside this warp)
    u64 mt[16];
    #pragma unroll
    for (int i = 0; i < 16; i++)
        mt[i] = add2_(add2_(m[0][i], m[1][i]), add2_(m[2][i], m[3][i]));
    u64 cp = pk2(cx, cy);
    #pragma unroll
    for (int off = 16; off > 0; off >>= 1){
        #pragma unroll
        for (int i = 0; i < 16; i++)
            mt[i] = add2_(mt[i], __shfl_xor_sync(0xffffffffu, mt[i], off));
        cp = add2_(cp, __shfl_xor_sync(0xffffffffu, cp, off));
    }
    if (lane < 16)
        ((u64*)(g_msum + (size_t)gi*DD))[lane] = mt[lane];
    if (lane == 0){
        float2 cf = upk2(cp);
        ((float2*)g_coors[cur^1])[gi] = make_float2(ci.x + cf.x, ci.y + cf.y);
    }
}

// ---------------- node MLP + residual (2 nodes/block) ----------------
__global__ void __launch_bounds__(128)
node_kernel(int cur, int last, float* __restrict__ dout,
            const float* __restrict__ n1w, const float* __restrict__ n1b,
            const float* __restrict__ n2w, const float* __restrict__ n2b){
    __shared__ float in[2][2*DD], h[2][2*DD];
    int t = threadIdx.x;
    int n = t >> 6, u = t & 63;
    int gi = blockIdx.x*2 + n;
    in[n][u] = (u < DD) ? g_feats[cur][gi*DD + u] : g_msum[gi*DD + (u - DD)];
    __syncthreads();
    float a = n1b[u];
    #pragma unroll
    for (int r = 0; r < 2*DD; r++) a += in[n][r]*n1w[r*64 + u];
    h[n][u] = lrelu(a);
    __syncthreads();
    if (u < DD){
        float o = n2b[u];
        #pragma unroll
        for (int r = 0; r < 2*DD; r++) o += h[n][r]*n2w[r*DD + u];
        o += in[n][u];
        if (last) dout[gi*DD + u] = o;
        else      g_feats[cur^1][gi*DD + u] = o;
    }
}

extern "C" void kernel_launch(void* const* d_in, const int* in_sizes, int n_in,
                              void* d_out, int out_size){
    const float* feat = (const float*)d_in[0];
    const float* coor = (const float*)d_in[1];
    // d_in[2] = batch (equal-size graphs; unused)
    const float* ew  = (const float*)d_in[3];
    const float* eb  = (const float*)d_in[4];
    const float* e1w = (const float*)d_in[5];
    const float* e1b = (const float*)d_in[6];
    const float* e2w = (const float*)d_in[7];
    const float* e2b = (const float*)d_in[8];
    const float* gw  = (const float*)d_in[9];
    const float* gb  = (const float*)d_in[10];
    const float* c1w = (const float*)d_in[11];
    const float* c1b = (const float*)d_in[12];
    const float* c2w = (const float*)d_in[13];
    const float* c2b = (const float*)d_in[14];
    const float* n1w = (const float*)d_in[15];
    const float* n1b = (const float*)d_in[16];
    const float* n2w = (const float*)d_in[17];
    const float* n2b = (const float*)d_in[18];
    const float* scl = (const float*)d_in[19];

    cudaMemcpyToSymbolAsync(g_coors, coor, BN*2*sizeof(float), 0,
                            cudaMemcpyDeviceToDevice, 0);
    embed_kernel<<<BN/4, 128>>>(feat, ew, eb);

    int cur = 0;
    for (int l = 0; l < 3; l++){
        knn_kernel<<<BN, 256>>>(cur);
        pre_kernel<<<BN/2, 264>>>(cur, e1w + l*65*EH, e1b + l*EH);
        edge_kernel<<<BN/4, 128>>>(cur,
                                 e1w + l*65*EH, e2w + l*EH*DD, e2b + l*DD,
                                 gw + l*DD, gb + l,
                                 c1w + l*DD*KK, c1b + l*KK,
                                 c2w + l*KK, c2b + l, scl + l);
        node_kernel<<<BN/2, 128>>>(cur, l == 2, (float*)d_out,
                                  n1w + l*64*64, n1b + l*64,
                                  n2w + l*64*DD, n2b + l*DD);
        cur ^= 1;
    }
}

// round 8
// speedup vs baseline: 2.2406x; 1.0050x over previous
#include <cuda_runtime.h>
#include <math.h>

#define BN 4096      // total nodes (B*N)
#define NN 1024      // nodes per graph
#define KK 128       // neighbours
#define DD 32        // feature dim
#define EH 130       // edge hidden
#define EHP 132      // padded edge hidden (mult of 4)

typedef unsigned long long u64;

__device__ float g_feats[2][BN*DD];
__device__ float g_coors[2][BN*2];
__device__ int   g_idx[BN*KK];
__device__ float g_dist[BN*KK];
__device__ float g_A[BN*EHP];
__device__ float g_Bv[BN*EHP];
__device__ float g_msum[BN*DD];

__device__ __forceinline__ float lrelu(float x){ return fmaxf(x, 0.1f*x); }

__device__ __forceinline__ u64 pk2(float lo, float hi){
    u64 r; asm("mov.b64 %0, {%1,%2};" : "=l"(r) : "f"(lo), "f"(hi)); return r;
}
__device__ __forceinline__ float2 upk2(u64 v){
    float2 f; asm("mov.b64 {%0,%1}, %2;" : "=f"(f.x), "=f"(f.y) : "l"(v)); return f;
}
__device__ __forceinline__ u64 fma2_(u64 a, u64 b, u64 c){
    u64 d; asm("fma.rn.f32x2 %0, %1, %2, %3;" : "=l"(d) : "l"(a), "l"(b), "l"(c)); return d;
}
__device__ __forceinline__ u64 add2_(u64 a, u64 b){
    u64 d; asm("add.rn.f32x2 %0, %1, %2;" : "=l"(d) : "l"(a), "l"(b)); return d;
}
__device__ __forceinline__ u64 mul2_(u64 a, u64 b){
    u64 d; asm("mul.rn.f32x2 %0, %1, %2;" : "=l"(d) : "l"(a), "l"(b)); return d;
}

// ---------------- embed + pre(layer 0): 2 nodes/block, 132 threads/node ----------------
__global__ void __launch_bounds__(264)
embed_pre_kernel(const float* __restrict__ feat,
                 const float* __restrict__ ew, const float* __restrict__ eb,
                 const float* __restrict__ e1w, const float* __restrict__ e1b){
    __shared__ float fin[2][DD], ff[2][DD];
    int t = threadIdx.x;
    int n = (t >= 132) ? 1 : 0;
    int u = t - n*132;
    int gi = blockIdx.x*2 + n;
    if (u < DD) fin[n][u] = feat[gi*DD + u];
    __syncthreads();
    if (u < DD){
        float a = eb[u];
        #pragma unroll
        for (int r = 0; r < DD; r++) a += fin[n][r]*ew[r*DD + u];
        float o = lrelu(a);
        g_feats[0][gi*DD + u] = o;
        ff[n][u] = o;
    }
    __syncthreads();
    float a = 0.f, bv = 0.f;
    if (u < EH){
        a = e1b[u];
        #pragma unroll
        for (int r = 0; r < DD; r++){
            float fr = ff[n][r];
            a  += fr * e1w[r*EH + u];
            bv += fr * e1w[(DD + r)*EH + u];
        }
    }
    g_A [gi*EHP + u] = a;
    g_Bv[gi*EHP + u] = bv;
}

// ---------------- knn: exact top-128 via 10-bit radix select ----------------
__global__ void __launch_bounds__(256) knn_kernel(int cur){
    __shared__ float2 sc[NN];
    __shared__ unsigned int hist[1024];
    __shared__ u64 cand[NN];
    __shared__ unsigned int sWarp[8][2];
    __shared__ unsigned int sScan[8];
    __shared__ unsigned int sT, sNeed;

    int gi = blockIdx.x, t = threadIdx.x;      // 256 threads
    int b = gi >> 10, il = gi & 1023;
    const float2* C = (const float2*)(g_coors[cur]) + b*NN;
    for (int x = t; x < NN; x += 256) sc[x] = C[x];
    for (int x = t; x < 1024; x += 256) hist[x] = 0u;
    __syncthreads();

    float2 ci = sc[il];
    u64 key[4]; unsigned bin[4];
    #pragma unroll
    for (int r = 0; r < 4; r++){
        int x = t + 256*r;
        float dx = ci.x - sc[x].x, dy = ci.y - sc[x].y;
        float d = dx*dx + dy*dy;
        unsigned db = __float_as_uint(d);
        key[r] = ((u64)db << 32) | (unsigned)x;
        bin[r] = min(db >> 22, 1023u);
        atomicAdd(&hist[bin[r]], 1u);
    }
    __syncthreads();

    unsigned lane = t & 31, w = t >> 5;
    unsigned local = hist[4*t] + hist[4*t+1] + hist[4*t+2] + hist[4*t+3];
    unsigned v = local;
    #pragma unroll
    for (int off = 1; off < 32; off <<= 1){
        unsigned nv = __shfl_up_sync(0xffffffffu, v, off);
        if (lane >= off) v += nv;
    }
    if (lane == 31) sScan[w] = v;
    __syncthreads();
    unsigned wb = 0;
    #pragma unroll
    for (int i = 0; i < 8; i++) if (i < (int)w) wb += sScan[i];
    unsigned run = wb + v - local;
    #pragma unroll
    for (int q = 0; q < 4; q++){
        unsigned h = hist[4*t + q];
        if (run <= 127u && run + h > 127u){ sT = 4*t + q; sNeed = 128u - run; }
        run += h;
    }
    __syncthreads();
    unsigned T = sT, need = sNeed;

    unsigned winbase = 0, candbase = 0;
    unsigned ltmask = (1u << lane) - 1u;
    #pragma unroll
    for (int r = 0; r < 4; r++){
        bool win = bin[r] < T;
        bool cd  = bin[r] == T;
        unsigned mw = __ballot_sync(0xffffffffu, win);
        unsigned mc = __ballot_sync(0xffffffffu, cd);
        if (lane == 0){ sWarp[w][0] = __popc(mw); sWarp[w][1] = __popc(mc); }
        __syncthreads();
        unsigned bw = winbase, bc = candbase, tw = 0, tc = 0;
        #pragma unroll
        for (int i = 0; i < 8; i++){
            unsigned cw_ = sWarp[i][0], cc_ = sWarp[i][1];
            if (i < (int)w){ bw += cw_; bc += cc_; }
            tw += cw_; tc += cc_;
        }
        if (win){
            unsigned pos = bw + __popc(mw & ltmask);
            g_idx [gi*KK + pos] = (int)(key[r] & 0xffffffffull);
            g_dist[gi*KK + pos] = __uint_as_float((unsigned)(key[r] >> 32));
        }
        if (cd){
            unsigned pos = bc + __popc(mc & ltmask);
            cand[pos] = key[r];
        }
        winbase += tw; candbase += tc;
        __syncthreads();
    }

    unsigned cntT = candbase;
    unsigned P = 2; while (P < cntT) P <<= 1;
    for (unsigned x = cntT + t; x < P; x += 256) cand[x] = 0xffffffffffffffffull;
    __syncthreads();
    for (unsigned k = 2; k <= P; k <<= 1){
        for (unsigned j = k >> 1; j > 0; j >>= 1){
            for (unsigned x = t; x < P; x += 256){
                unsigned ixj = x ^ j;
                if (ixj > x){
                    u64 a = cand[x], bb = cand[ixj];
                    bool up = (x & k) == 0;
                    if ((a > bb) == up){ cand[x] = bb; cand[ixj] = a; }
                }
            }
            __syncthreads();
        }
    }
    if (t < need){
        u64 kv = cand[t];
        unsigned pos = winbase + t;
        g_idx [gi*KK + pos] = (int)(kv & 0xffffffffull);
        g_dist[gi*KK + pos] = __uint_as_float((unsigned)(kv >> 32));
    }
}

// ---------------- edge kernel: 4 nodes/block (1 warp each), 4 edges/thread ----------------
// Software-pipelined Bv stream; tail unrolled x2 over c1 rows for ILP.
__global__ void __launch_bounds__(128)
edge_kernel(int cur,
            const float* __restrict__ e1w, const float* __restrict__ e2w,
            const float* __restrict__ e2b, const float* __restrict__ gw,
            const float* __restrict__ gb,  const float* __restrict__ c1w,
            const float* __restrict__ c1b, const float* __restrict__ c2w,
            const float* __restrict__ c2b, const float* __restrict__ scl){
    __shared__ __align__(16) float sW2[EHP*DD];     // e2 weights [u][dd]
    __shared__ __align__(16) float sC1t[KK*36];     // c1 transposed [v][dd], stride 36
    __shared__ __align__(16) float sA[4][EHP];
    __shared__ __align__(16) float sW1c[EHP];
    __shared__ __align__(16) float sC2[KK];
    __shared__ __align__(16) float sC1b[KK];
    __shared__ __align__(16) float sGw[DD];
    __shared__ __align__(16) float sE2b[DD];

    int t = threadIdx.x;
    int w = t >> 5;                    // warp = node within block
    int lane = t & 31;
    int gi = blockIdx.x*4 + w;
    int b = gi >> 10;

    for (int x = t; x < EHP*DD; x += 128) sW2[x] = (x < EH*DD) ? e2w[x] : 0.f;
    for (int x = t; x < DD*KK; x += 128){ int dd = x >> 7, v = x & 127; sC1t[v*36 + dd] = c1w[x]; }
    for (int x = t; x < 4*EHP; x += 128){
        int n = x / EHP, u = x - n*EHP;
        sA[n][u] = g_A[(blockIdx.x*4 + n)*EHP + u];
    }
    for (int x = t; x < EHP; x += 128) sW1c[x] = (x < EH) ? e1w[64*EH + x] : 0.f;
    if (t < KK){ sC2[t] = c2w[t]; sC1b[t] = c1b[t]; }
    if (t < DD){ sGw[t] = gw[t]; sE2b[t] = e2b[t]; }
    __syncthreads();

    int   j[4]; float d[4];
    #pragma unroll
    for (int q = 0; q < 4; q++){
        j[q] = g_idx [gi*KK + lane + 32*q];
        d[q] = g_dist[gi*KK + lane + 32*q];
    }
    const float4* bvP[4];
    #pragma unroll
    for (int q = 0; q < 4; q++)
        bvP[q] = (const float4*)(g_Bv + (size_t)(b*NN + j[q])*EHP);

    const float4* a4p = (const float4*)(sA[w]);
    const float4* w4p = (const float4*)(sW1c);
    const u64* gw2 = (const u64*)sGw;

    u64 m[4][16];
    {
        const u64* b2 = (const u64*)sE2b;
        #pragma unroll
        for (int q = 0; q < 4; q++)
            #pragma unroll
            for (int i = 0; i < 16; i++) m[q][i] = b2[i];
    }

    // software-pipelined main loop
    float4 bvCur[4];
    #pragma unroll
    for (int q = 0; q < 4; q++) bvCur[q] = bvP[q][0];

    #pragma unroll 1
    for (int g = 0; g < EHP/4; g++){
        float4 bvNext[4];
        if (g + 1 < EHP/4){
            #pragma unroll
            for (int q = 0; q < 4; q++) bvNext[q] = bvP[q][g+1];
        }
        float4 aa = a4p[g], wc = w4p[g];
        float av[4] = {aa.x, aa.y, aa.z, aa.w};
        float wv[4] = {wc.x, wc.y, wc.z, wc.w};
        float bv[4][4];
        #pragma unroll
        for (int q = 0; q < 4; q++){
            bv[q][0] = bvCur[q].x; bv[q][1] = bvCur[q].y;
            bv[q][2] = bvCur[q].z; bv[q][3] = bvCur[q].w;
        }
        #pragma unroll
        for (int s = 0; s < 4; s++){
            int u = 4*g + s;
            u64 h2[4];
            #pragma unroll
            for (int q = 0; q < 4; q++){
                float h = lrelu(fmaf(d[q], wv[s], av[s]) + bv[q][s]);
                h2[q] = pk2(h, h);
            }
            const ulonglong2* w2 = (const ulonglong2*)(sW2 + u*DD);
            #pragma unroll
            for (int k = 0; k < 8; k++){
                ulonglong2 ww = w2[k];
                #pragma unroll
                for (int q = 0; q < 4; q++){
                    m[q][2*k]   = fma2_(h2[q], ww.x, m[q][2*k]);
                    m[q][2*k+1] = fma2_(h2[q], ww.y, m[q][2*k+1]);
                }
            }
        }
        #pragma unroll
        for (int q = 0; q < 4; q++) bvCur[q] = bvNext[q];
    }

    // lrelu on messages
    #pragma unroll
    for (int q = 0; q < 4; q++)
        #pragma unroll
        for (int i = 0; i < 16; i++){
            float2 f = upk2(m[q][i]);
            m[q][i] = pk2(lrelu(f.x), lrelu(f.y));
        }

    // soft-edge gates
    float gb0 = gb[0];
    {
        u64 acc[4] = {0ull,0ull,0ull,0ull};
        #pragma unroll
        for (int i = 0; i < 16; i++){
            u64 gwv = gw2[i];
            #pragma unroll
            for (int q = 0; q < 4; q++) acc[q] = fma2_(m[q][i], gwv, acc[q]);
        }
        #pragma unroll
        for (int q = 0; q < 4; q++){
            float2 a = upk2(acc[q]);
            float sg = 1.f/(1.f + expf(-(gb0 + a.x + a.y)));
            u64 sg2 = pk2(sg, sg);
            #pragma unroll
            for (int i = 0; i < 16; i++) m[q][i] = mul2_(m[q][i], sg2);
        }
    }

    // coors MLP -> per-edge scalar weight; 2 c1 rows per iteration for ILP
    float c2b0 = c2b[0];
    float cw[4] = {c2b0, c2b0, c2b0, c2b0};
    #pragma unroll 1
    for (int vp = 0; vp < KK/2; vp++){
        const ulonglong2* ccA = (const ulonglong2*)(sC1t + (2*vp)*36);
        const ulonglong2* ccB = (const ulonglong2*)(sC1t + (2*vp+1)*36);
        u64 sa[4] = {0ull,0ull,0ull,0ull};
        u64 sb[4] = {0ull,0ull,0ull,0ull};
        #pragma unroll
        for (int k = 0; k < 8; k++){
            ulonglong2 wa = ccA[k], wb = ccB[k];
            #pragma unroll
            for (int q = 0; q < 4; q++){
                sa[q] = fma2_(m[q][2*k],   wa.x, sa[q]);
                sa[q] = fma2_(m[q][2*k+1], wa.y, sa[q]);
                sb[q] = fma2_(m[q][2*k],   wb.x, sb[q]);
                sb[q] = fma2_(m[q][2*k+1], wb.y, sb[q]);
            }
        }
        float2 cb2 = ((const float2*)sC1b)[vp];
        float2 c22 = ((const float2*)sC2)[vp];
        #pragma unroll
        for (int q = 0; q < 4; q++){
            float2 fa = upk2(sa[q]), fb = upk2(sb[q]);
            cw[q] += lrelu(cb2.x + fa.x + fa.y)*c22.x;
            cw[q] += lrelu(cb2.y + fb.x + fb.y)*c22.y;
        }
    }

    // coordinate contributions
    const float2* Cg = (const float2*)(g_coors[cur]);
    float2 ci = Cg[gi];
    float sscl = scl[0];
    float cx = 0.f, cy = 0.f;
    #pragma unroll
    for (int q = 0; q < 4; q++){
        float2 cj = Cg[b*NN + j[q]];
        float rx = ci.x - cj.x, ry = ci.y - cj.y;
        float nm = fmaxf(sqrtf(rx*rx + ry*ry), 1e-8f);
        float ss = sscl/nm;
        cx += cw[q]*(rx*ss);
        cy += cw[q]*(ry*ss);
    }

    // warp-level reduction (node fully inside this warp)
    u64 mt[16];
    #pragma unroll
    for (int i = 0; i < 16; i++)
        mt[i] = add2_(add2_(m[0][i], m[1][i]), add2_(m[2][i], m[3][i]));
    u64 cp = pk2(cx, cy);
    #pragma unroll
    for (int off = 16; off > 0; off >>= 1){
        #pragma unroll
        for (int i = 0; i < 16; i++)
            mt[i] = add2_(mt[i], __shfl_xor_sync(0xffffffffu, mt[i], off));
        cp = add2_(cp, __shfl_xor_sync(0xffffffffu, cp, off));
    }
    if (lane < 16)
        ((u64*)(g_msum + (size_t)gi*DD))[lane] = mt[lane];
    if (lane == 0){
        float2 cf = upk2(cp);
        ((float2*)g_coors[cur^1])[gi] = make_float2(ci.x + cf.x, ci.y + cf.y);
    }
}

// ---------------- node MLP + residual, fused with pre of next layer ----------------
// 2 nodes/block, 132 threads per node.
__global__ void __launch_bounds__(264)
node_pre_kernel(int cur, int last, float* __restrict__ dout,
                const float* __restrict__ n1w, const float* __restrict__ n1b,
                const float* __restrict__ n2w, const float* __restrict__ n2b,
                const float* __restrict__ e1w, const float* __restrict__ e1b){
    __shared__ float in[2][2*DD], h[2][2*DD], ff[2][DD];
    int t = threadIdx.x;
    int n = (t >= 132) ? 1 : 0;
    int u = t - n*132;
    int gi = blockIdx.x*2 + n;
    if (u < 2*DD)
        in[n][u] = (u < DD) ? g_feats[cur][gi*DD + u] : g_msum[gi*DD + (u - DD)];
    __syncthreads();
    if (u < 2*DD){
        float a = n1b[u];
        #pragma unroll
        for (int r = 0; r < 2*DD; r++) a += in[n][r]*n1w[r*64 + u];
        h[n][u] = lrelu(a);
    }
    __syncthreads();
    if (u < DD){
        float o = n2b[u];
        #pragma unroll
        for (int r = 0; r < 2*DD; r++) o += h[n][r]*n2w[r*DD + u];
        o += in[n][u];
        if (last) dout[gi*DD + u] = o;
        else { g_feats[cur^1][gi*DD + u] = o; ff[n][u] = o; }
    }
    if (last) return;                 // uniform across block
    __syncthreads();
    float a = 0.f, bv = 0.f;
    if (u < EH){
        a = e1b[u];
        #pragma unroll
        for (int r = 0; r < DD; r++){
            float fr = ff[n][r];
            a  += fr * e1w[r*EH + u];
            bv += fr * e1w[(DD + r)*EH + u];
        }
    }
    g_A [gi*EHP + u] = a;
    g_Bv[gi*EHP + u] = bv;
}

extern "C" void kernel_launch(void* const* d_in, const int* in_sizes, int n_in,
                              void* d_out, int out_size){
    const float* feat = (const float*)d_in[0];
    const float* coor = (const float*)d_in[1];
    // d_in[2] = batch (equal-size graphs; unused)
    const float* ew  = (const float*)d_in[3];
    const float* eb  = (const float*)d_in[4];
    const float* e1w = (const float*)d_in[5];
    const float* e1b = (const float*)d_in[6];
    const float* e2w = (const float*)d_in[7];
    const float* e2b = (const float*)d_in[8];
    const float* gw  = (const float*)d_in[9];
    const float* gb  = (const float*)d_in[10];
    const float* c1w = (const float*)d_in[11];
    const float* c1b = (const float*)d_in[12];
    const float* c2w = (const float*)d_in[13];
    const float* c2b = (const float*)d_in[14];
    const float* n1w = (const float*)d_in[15];
    const float* n1b = (const float*)d_in[16];
    const float* n2w = (const float*)d_in[17];
    const float* n2b = (const float*)d_in[18];
    const float* scl = (const float*)d_in[19];

    cudaMemcpyToSymbolAsync(g_coors, coor, BN*2*sizeof(float), 0,
                            cudaMemcpyDeviceToDevice, 0);
    embed_pre_kernel<<<BN/2, 264>>>(feat, ew, eb, e1w, e1b);

    int cur = 0;
    for (int l = 0; l < 3; l++){
        int nl = (l < 2) ? (l + 1) : l;   // e1 weights for the NEXT layer's pre
        knn_kernel<<<BN, 256>>>(cur);
        edge_kernel<<<BN/4, 128>>>(cur,
                                 e1w + l*65*EH, e2w + l*EH*DD, e2b + l*DD,
                                 gw + l*DD, gb + l,
                                 c1w + l*DD*KK, c1b + l*KK,
                                 c2w + l*KK, c2b + l, scl + l);
        node_pre_kernel<<<BN/2, 264>>>(cur, l == 2, (float*)d_out,
                                  n1w + l*64*64, n1b + l*64,
                                  n2w + l*64*DD, n2b + l*DD,
                                  e1w + nl*65*EH, e1b + nl*EH);
        cur ^= 1;
    }
}